// round 10
// baseline (speedup 1.0000x reference)
#include <cuda_runtime.h>
#include <cuda_bf16.h>
#include <cstdint>

// ---------------------------------------------------------------------------
// MHA block using tensor cores via mma.sync (bf16, sm_80-generic PTX -> HMMA),
// split-bf16 (hi+lo) operands: each GEMM = 3 MMAs (hh + hl + lh) -> f32 acc.
// R10 fix: gemm K-loop covers all 16 BK=32 stages (K=512), was 8 (K=256).
// ---------------------------------------------------------------------------

using bf16 = __nv_bfloat16;
typedef unsigned int u32;
typedef unsigned long long u64;

namespace {
constexpr int B = 4, S = 2048, D = 512, H = 8, BH = 32, MTOK = 8192;
constexpr long long OUT_ELEMS  = (long long)MTOK * D;
constexpr long long ATTN_ELEMS = (long long)BH * S * (long long)S;

// gemm/scores smem: 4 tiles of 128 rows x 80B (32 bf16 + pad)
constexpr int A_HI = 0, A_LO = 10240, SB_HI = 20480, SB_LO = 30720;
constexpr int SM_GEMM = 40960;
// pv smem: P 128x80B hi/lo, V 32x144B hi/lo, rinv 128 f32
constexpr int P_HI = 0, P_LO = 10240, V_HI = 20480, V_LO = 25088, RINV = 29696;
constexpr int SM_PV = 30208;
}

// ---- device scratch (allocation-free rule) ---------------------------------
__device__ bf16  g_W[4][2][(size_t)D * D];     // Wq,Wk,Wv,Wo transposed hi/lo
__device__ bf16  g_Qs[2][(size_t)MTOK * D];
__device__ bf16  g_Ks[2][(size_t)MTOK * D];
__device__ bf16  g_Vs[2][(size_t)MTOK * D];
__device__ bf16  g_Os[2][(size_t)MTOK * D];
__device__ float g_Y[(size_t)MTOK * D];
__device__ float g_rowsum[BH * S];
__device__ float g_attn_fb[(size_t)BH * S * (size_t)S];

// ---- PTX helpers ------------------------------------------------------------
__device__ __forceinline__ u32 cvta_smem(const void* p) {
    u32 a;
    asm("{ .reg .u64 t; cvta.to.shared.u64 t, %1; cvt.u32.u64 %0, t; }"
        : "=r"(a) : "l"(p));
    return a;
}
__device__ __forceinline__ void ldsm4(u32& r0, u32& r1, u32& r2, u32& r3, u32 a) {
    asm volatile("ldmatrix.sync.aligned.m8n8.x4.shared.b16 {%0,%1,%2,%3}, [%4];"
                 : "=r"(r0), "=r"(r1), "=r"(r2), "=r"(r3) : "r"(a));
}
__device__ __forceinline__ void ldsm2(u32& r0, u32& r1, u32 a) {
    asm volatile("ldmatrix.sync.aligned.m8n8.x2.shared.b16 {%0,%1}, [%2];"
                 : "=r"(r0), "=r"(r1) : "r"(a));
}
__device__ __forceinline__ void ldsm2t(u32& r0, u32& r1, u32 a) {
    asm volatile("ldmatrix.sync.aligned.m8n8.x2.trans.shared.b16 {%0,%1}, [%2];"
                 : "=r"(r0), "=r"(r1) : "r"(a));
}
__device__ __forceinline__ void mma_bb(float* c, const u32* a, const u32* b) {
    asm volatile(
        "mma.sync.aligned.m16n8k16.row.col.f32.bf16.bf16.f32 "
        "{%0,%1,%2,%3}, {%4,%5,%6,%7}, {%8,%9}, {%0,%1,%2,%3};"
        : "+f"(c[0]), "+f"(c[1]), "+f"(c[2]), "+f"(c[3])
        : "r"(a[0]), "r"(a[1]), "r"(a[2]), "r"(a[3]), "r"(b[0]), "r"(b[1]));
}

// ---- split / pack ------------------------------------------------------------
__device__ __forceinline__ void split1(float x, bf16& h, bf16& l) {
    h = __float2bfloat16(x);
    l = __float2bfloat16(x - __bfloat162float(h));
}
__device__ __forceinline__ u32 pack2(bf16 a, bf16 b) {
    return (u32)__bfloat16_as_ushort(a) | ((u32)__bfloat16_as_ushort(b) << 16);
}
__device__ __forceinline__ void split8(float4 v0, float4 v1, uint4& hi, uint4& lo) {
    bf16 ha, la, hb, lb;
    split1(v0.x, ha, la); split1(v0.y, hb, lb); hi.x = pack2(ha, hb); lo.x = pack2(la, lb);
    split1(v0.z, ha, la); split1(v0.w, hb, lb); hi.y = pack2(ha, hb); lo.y = pack2(la, lb);
    split1(v1.x, ha, la); split1(v1.y, hb, lb); hi.z = pack2(ha, hb); lo.z = pack2(la, lb);
    split1(v1.z, ha, la); split1(v1.w, hb, lb); hi.w = pack2(ha, hb); lo.w = pack2(la, lb);
}

// Shared inner compute: one BK=32 stage, warp tile 64x32 (MT=4, NT=4).
__device__ __forceinline__ void compute32_44(float acc[4][4][4], u32 sb,
                                             int m0w, int n0w, int lane)
{
    const int la15 = lane & 15, lc = lane >> 4;
    const int l7 = lane & 7, lb = (lane >> 3) & 1;
#pragma unroll
    for (int ks = 0; ks < 2; ks++) {
        const u32 ko = (u32)(ks * 32);
        u32 ah[4][4], al[4][4];
#pragma unroll
        for (int mt = 0; mt < 4; mt++) {
            u32 a = sb + A_HI + (u32)((m0w + mt * 16 + la15) * 80) + ko + lc * 16;
            ldsm4(ah[mt][0], ah[mt][1], ah[mt][2], ah[mt][3], a);
            ldsm4(al[mt][0], al[mt][1], al[mt][2], al[mt][3], a + (A_LO - A_HI));
        }
        u32 bh_[4][2], bl_[4][2];
#pragma unroll
        for (int nt = 0; nt < 4; nt++) {
            u32 a = sb + SB_HI + (u32)((n0w + nt * 8 + l7) * 80) + ko + lb * 16;
            ldsm2(bh_[nt][0], bh_[nt][1], a);
            ldsm2(bl_[nt][0], bl_[nt][1], a + (SB_LO - SB_HI));
        }
#pragma unroll
        for (int mt = 0; mt < 4; mt++)
#pragma unroll
            for (int nt = 0; nt < 4; nt++) {
                mma_bb(acc[mt][nt], ah[mt], bh_[nt]);
                mma_bb(acc[mt][nt], ah[mt], bl_[nt]);
                mma_bb(acc[mt][nt], al[mt], bh_[nt]);
            }
    }
}

// ---------------------------------------------------------------------------
// Weight prep: W[k][n] (f32 512x512) -> W^T hi/lo bf16 [n][k]
// ---------------------------------------------------------------------------
__global__ void wsplit_k(const float* __restrict__ w,
                         bf16* __restrict__ hi, bf16* __restrict__ lo) {
    int i = blockIdx.x * 256 + threadIdx.x;
    int k = i >> 9, n = i & 511;
    bf16 h, l; split1(w[i], h, l);
    hi[(size_t)n * 512 + k] = h;
    lo[(size_t)n * 512 + k] = l;
}

// ---------------------------------------------------------------------------
// Split-bf16 GEMM (K=512): 128x128 block tile, 256 thr, 8 warps (2m x 4n).
// MODE 0: C -> bf16 hi/lo pair;  MODE 2: C + residual R -> f32 Yf.
// A from f32 (Af) or bf16 pair (Ahi/Alo). B always bf16 pair [n][k].
// ---------------------------------------------------------------------------
template<int MODE>
__global__ __launch_bounds__(256)
void gemm_bs(const float* __restrict__ Af,
             const bf16* __restrict__ Ahi, const bf16* __restrict__ Alo,
             const bf16* __restrict__ Bhi, const bf16* __restrict__ Blo,
             bf16* __restrict__ Chi, bf16* __restrict__ Clo,
             const float* __restrict__ R, float* __restrict__ Yf)
{
    __shared__ __align__(16) char sm[SM_GEMM];
    const int tid = threadIdx.x, lane = tid & 31, wi = tid >> 5;
    const int m0 = blockIdx.y * 128, n0 = blockIdx.x * 128;
    const int m0w = (wi >> 2) * 64, n0w = (wi & 3) * 32;
    const u32 sb = cvta_smem(sm);
    const int r = tid >> 1, hf = tid & 1;
    const u32 soff = (u32)(r * 80 + hf * 32);

    float acc[4][4][4];
#pragma unroll
    for (int i = 0; i < 4; i++)
#pragma unroll
        for (int j = 0; j < 4; j++)
#pragma unroll
            for (int q = 0; q < 4; q++) acc[i][j][q] = 0.f;

    for (int c = 0; c < 16; c++) {          // FIXED: 16 stages x BK=32 = K=512
        const int k0 = c * 32;
        if (Af) {
            const float4* ap = (const float4*)(Af + (size_t)(m0 + r) * 512 + k0 + hf * 16);
            uint4 h0, l0, h1, l1;
            split8(ap[0], ap[1], h0, l0);
            split8(ap[2], ap[3], h1, l1);
            *(uint4*)(sm + A_HI + soff)      = h0;
            *(uint4*)(sm + A_HI + soff + 16) = h1;
            *(uint4*)(sm + A_LO + soff)      = l0;
            *(uint4*)(sm + A_LO + soff + 16) = l1;
        } else {
            const uint4* ph = (const uint4*)(Ahi + (size_t)(m0 + r) * 512 + k0 + hf * 16);
            const uint4* pl = (const uint4*)(Alo + (size_t)(m0 + r) * 512 + k0 + hf * 16);
            *(uint4*)(sm + A_HI + soff)      = ph[0];
            *(uint4*)(sm + A_HI + soff + 16) = ph[1];
            *(uint4*)(sm + A_LO + soff)      = pl[0];
            *(uint4*)(sm + A_LO + soff + 16) = pl[1];
        }
        {
            const uint4* ph = (const uint4*)(Bhi + (size_t)(n0 + r) * 512 + k0 + hf * 16);
            const uint4* pl = (const uint4*)(Blo + (size_t)(n0 + r) * 512 + k0 + hf * 16);
            *(uint4*)(sm + SB_HI + soff)      = ph[0];
            *(uint4*)(sm + SB_HI + soff + 16) = ph[1];
            *(uint4*)(sm + SB_LO + soff)      = pl[0];
            *(uint4*)(sm + SB_LO + soff + 16) = pl[1];
        }
        __syncthreads();
        compute32_44(acc, sb, m0w, n0w, lane);
        __syncthreads();
    }

    const int g = lane >> 2, tg = lane & 3;
#pragma unroll
    for (int mt = 0; mt < 4; mt++)
#pragma unroll
        for (int h2 = 0; h2 < 2; h2++) {
            const size_t m = (size_t)(m0 + m0w + mt * 16 + h2 * 8 + g);
#pragma unroll
            for (int nt = 0; nt < 4; nt++) {
                const int ncol = n0 + n0w + nt * 8 + tg * 2;
                const float x0 = acc[mt][nt][h2 * 2], x1 = acc[mt][nt][h2 * 2 + 1];
                if (MODE == 0) {
                    bf16 h0, l0, h1, l1;
                    split1(x0, h0, l0); split1(x1, h1, l1);
                    *(u32*)(Chi + m * 512 + ncol) = pack2(h0, h1);
                    *(u32*)(Clo + m * 512 + ncol) = pack2(l0, l1);
                } else {
                    const float2 rv = *(const float2*)(R + m * 512 + ncol);
                    *(float2*)(Yf + m * 512 + ncol) = make_float2(x0 + rv.x, x1 + rv.y);
                }
            }
        }
}

// ---------------------------------------------------------------------------
// Scores: exp(mask ? -inf : QK^T/8) unnormalized -> attn(f32) + rowsums.
// One CTA = 128q x 128k of one (b,h); DK=64 = two BK=32 stages.
// ---------------------------------------------------------------------------
__global__ __launch_bounds__(256)
void scores_bs(const bf16* __restrict__ Qhi, const bf16* __restrict__ Qlo,
               const bf16* __restrict__ Khi, const bf16* __restrict__ Klo,
               const unsigned char* __restrict__ mask,
               float* __restrict__ attn, float* __restrict__ rowsum)
{
    __shared__ __align__(16) char sm[SM_GEMM];
    const int tid = threadIdx.x, lane = tid & 31, wi = tid >> 5;
    const int bh = blockIdx.z, b_ = bh >> 3, h_ = bh & 7;
    const int q0 = blockIdx.y * 128, kt0 = blockIdx.x * 128;
    const int m0w = (wi >> 2) * 64, n0w = (wi & 3) * 32;
    const u32 sb = cvta_smem(sm);
    const int r = tid >> 1, hf = tid & 1;
    const u32 soff = (u32)(r * 80 + hf * 32);

    float acc[4][4][4];
#pragma unroll
    for (int i = 0; i < 4; i++)
#pragma unroll
        for (int j = 0; j < 4; j++)
#pragma unroll
            for (int q = 0; q < 4; q++) acc[i][j][q] = 0.f;

#pragma unroll
    for (int c = 0; c < 2; c++) {
        const int k0 = h_ * 64 + c * 32;
        {
            const size_t ab = (size_t)(b_ * S + q0 + r) * 512 + k0 + hf * 16;
            const uint4* ph = (const uint4*)(Qhi + ab);
            const uint4* pl = (const uint4*)(Qlo + ab);
            *(uint4*)(sm + A_HI + soff)      = ph[0];
            *(uint4*)(sm + A_HI + soff + 16) = ph[1];
            *(uint4*)(sm + A_LO + soff)      = pl[0];
            *(uint4*)(sm + A_LO + soff + 16) = pl[1];
        }
        {
            const size_t bb = (size_t)(b_ * S + kt0 + r) * 512 + k0 + hf * 16;
            const uint4* ph = (const uint4*)(Khi + bb);
            const uint4* pl = (const uint4*)(Klo + bb);
            *(uint4*)(sm + SB_HI + soff)      = ph[0];
            *(uint4*)(sm + SB_HI + soff + 16) = ph[1];
            *(uint4*)(sm + SB_LO + soff)      = pl[0];
            *(uint4*)(sm + SB_LO + soff + 16) = pl[1];
        }
        __syncthreads();
        compute32_44(acc, sb, m0w, n0w, lane);
        __syncthreads();
    }

    const int g = lane >> 2, tg = lane & 3;
#pragma unroll
    for (int mt = 0; mt < 4; mt++)
#pragma unroll
        for (int h2 = 0; h2 < 2; h2++) {
            const int q = q0 + m0w + mt * 16 + h2 * 8 + g;
            const unsigned char* mrow = mask + (size_t)(b_ * S + q) * S + kt0;
            float* arow = attn + ((size_t)bh * S + q) * S + kt0;
            float rs = 0.f;
#pragma unroll
            for (int nt = 0; nt < 4; nt++) {
                const int col = n0w + nt * 8 + tg * 2;
                const unsigned short mv = *(const unsigned short*)(mrow + col);
                const float s0 = acc[mt][nt][h2 * 2]     * 0.125f;
                const float s1 = acc[mt][nt][h2 * 2 + 1] * 0.125f;
                const float e0 = (mv & 0xff) ? 0.f : __expf(s0);
                const float e1 = (mv >> 8)   ? 0.f : __expf(s1);
                *(float2*)(arow + col) = make_float2(e0, e1);
                rs += e0 + e1;
            }
            rs += __shfl_xor_sync(0xffffffffu, rs, 1);
            rs += __shfl_xor_sync(0xffffffffu, rs, 2);
            if (tg == 0) atomicAdd(&rowsum[(size_t)bh * S + q], rs);
        }
}

// ---------------------------------------------------------------------------
// PV: normalize attn in place (final output #2) and O = P @ V (N=64).
// One CTA = 128 q-rows of one (b,h); 64 chunks of 32 keys.
// Warp tile 32x32 (MT=2, NT=4); V fragments via ldmatrix.trans.
// ---------------------------------------------------------------------------
__global__ __launch_bounds__(256)
void pv_bs(float* __restrict__ attn,
           const bf16* __restrict__ Vhi, const bf16* __restrict__ Vlo,
           const float* __restrict__ rowsum,
           bf16* __restrict__ Ohi, bf16* __restrict__ Olo)
{
    __shared__ __align__(16) char sm[SM_PV];
    const int tid = threadIdx.x, lane = tid & 31, wi = tid >> 5;
    const int bh = blockIdx.y, b_ = bh >> 3, h_ = bh & 7;
    const int q0 = blockIdx.x * 128;
    const int m0w = (wi >> 1) * 32, n0w = (wi & 1) * 32;
    const u32 sb = cvta_smem(sm);
    float* rinv_s = (float*)(sm + RINV);
    if (tid < 128) rinv_s[tid] = 1.0f / rowsum[(size_t)bh * S + q0 + tid];
    __syncthreads();

    const int r = tid >> 1, hf = tid & 1;
    const u32 soff = (u32)(r * 80 + hf * 32);
    const int vr = tid >> 3, vc = tid & 7;          // V stage: 32 rows x 8 chunks
    float* arow = attn + ((size_t)bh * S + q0 + r) * S + hf * 16;
    const float rv = rinv_s[r];

    float acc[2][4][4];
#pragma unroll
    for (int i = 0; i < 2; i++)
#pragma unroll
        for (int j = 0; j < 4; j++)
#pragma unroll
            for (int q = 0; q < 4; q++) acc[i][j][q] = 0.f;

    const int la15 = lane & 15, lc = lane >> 4;

    for (int c = 0; c < 64; c++) {
        const int kt = c * 32;
        {   // P stage: load attn, normalize, write back (final), split to smem
            float4* gp = (float4*)(arow + kt);
            float4 v0 = gp[0], v1 = gp[1], v2 = gp[2], v3 = gp[3];
            v0.x *= rv; v0.y *= rv; v0.z *= rv; v0.w *= rv;
            v1.x *= rv; v1.y *= rv; v1.z *= rv; v1.w *= rv;
            v2.x *= rv; v2.y *= rv; v2.z *= rv; v2.w *= rv;
            v3.x *= rv; v3.y *= rv; v3.z *= rv; v3.w *= rv;
            gp[0] = v0; gp[1] = v1; gp[2] = v2; gp[3] = v3;
            uint4 h0, l0, h1, l1;
            split8(v0, v1, h0, l0);
            split8(v2, v3, h1, l1);
            *(uint4*)(sm + P_HI + soff)      = h0;
            *(uint4*)(sm + P_HI + soff + 16) = h1;
            *(uint4*)(sm + P_LO + soff)      = l0;
            *(uint4*)(sm + P_LO + soff + 16) = l1;
        }
        {   // V stage: 32 (s) x 64 (d) hi/lo
            const size_t vb = (size_t)(b_ * S + kt + vr) * 512 + h_ * 64 + vc * 8;
            const u32 vo = (u32)(vr * 144 + vc * 16);
            *(uint4*)(sm + V_HI + vo) = *(const uint4*)(Vhi + vb);
            *(uint4*)(sm + V_LO + vo) = *(const uint4*)(Vlo + vb);
        }
        __syncthreads();
#pragma unroll
        for (int ks = 0; ks < 2; ks++) {
            const u32 ko = (u32)(ks * 32);
            u32 ah[2][4], al[2][4];
#pragma unroll
            for (int mt = 0; mt < 2; mt++) {
                u32 a = sb + P_HI + (u32)((m0w + mt * 16 + la15) * 80) + ko + lc * 16;
                ldsm4(ah[mt][0], ah[mt][1], ah[mt][2], ah[mt][3], a);
                ldsm4(al[mt][0], al[mt][1], al[mt][2], al[mt][3], a + (P_LO - P_HI));
            }
            u32 bh_[4][2], bl_[4][2];
#pragma unroll
            for (int nt = 0; nt < 4; nt++) {
                u32 a = sb + V_HI + (u32)((ks * 16 + la15) * 144 + (n0w + nt * 8) * 2);
                ldsm2t(bh_[nt][0], bh_[nt][1], a);
                ldsm2t(bl_[nt][0], bl_[nt][1], a + (V_LO - V_HI));
            }
#pragma unroll
            for (int mt = 0; mt < 2; mt++)
#pragma unroll
                for (int nt = 0; nt < 4; nt++) {
                    mma_bb(acc[mt][nt], ah[mt], bh_[nt]);
                    mma_bb(acc[mt][nt], ah[mt], bl_[nt]);
                    mma_bb(acc[mt][nt], al[mt], bh_[nt]);
                }
        }
        __syncthreads();
    }

    const int g = lane >> 2, tg = lane & 3;
#pragma unroll
    for (int mt = 0; mt < 2; mt++)
#pragma unroll
        for (int h2 = 0; h2 < 2; h2++) {
            const size_t m = (size_t)(b_ * S + q0 + m0w + mt * 16 + h2 * 8 + g);
#pragma unroll
            for (int nt = 0; nt < 4; nt++) {
                const int ncol = h_ * 64 + n0w + nt * 8 + tg * 2;
                bf16 h0, l0, h1, l1;
                split1(acc[mt][nt][h2 * 2],     h0, l0);
                split1(acc[mt][nt][h2 * 2 + 1], h1, l1);
                *(u32*)(Ohi + m * 512 + ncol) = pack2(h0, h1);
                *(u32*)(Olo + m * 512 + ncol) = pack2(l0, l1);
            }
        }
}

// ---------------------------------------------------------------------------
// Row LayerNorm: 1 block (128 threads) per row of 512.
// ---------------------------------------------------------------------------
__global__ __launch_bounds__(128)
void ln_k(const float* __restrict__ X, const float* __restrict__ gam,
          const float* __restrict__ bet, float* __restrict__ out)
{
    __shared__ float red[4];
    const int row = blockIdx.x, tid = threadIdx.x;
    const int lane = tid & 31, wid = tid >> 5;
    const float4 x = *(const float4*)(X + (size_t)row * D + tid * 4);

    float s = x.x + x.y + x.z + x.w;
#pragma unroll
    for (int off = 16; off > 0; off >>= 1) s += __shfl_xor_sync(~0u, s, off);
    if (lane == 0) red[wid] = s;
    __syncthreads();
    const float mu = (red[0] + red[1] + red[2] + red[3]) * (1.0f / D);
    __syncthreads();

    const float4 dx = make_float4(x.x - mu, x.y - mu, x.z - mu, x.w - mu);
    float q = dx.x * dx.x + dx.y * dx.y + dx.z * dx.z + dx.w * dx.w;
#pragma unroll
    for (int off = 16; off > 0; off >>= 1) q += __shfl_xor_sync(~0u, q, off);
    if (lane == 0) red[wid] = q;
    __syncthreads();
    const float var = (red[0] + red[1] + red[2] + red[3]) * (1.0f / D);
    const float inv = rsqrtf(var + 1e-5f);

    const float4 g  = *(const float4*)(gam + tid * 4);
    const float4 bb = *(const float4*)(bet + tid * 4);
    float4 y;
    y.x = dx.x * inv * g.x + bb.x;
    y.y = dx.y * inv * g.y + bb.y;
    y.z = dx.z * inv * g.z + bb.z;
    y.w = dx.w * inv * g.w + bb.w;
    *(float4*)(out + (size_t)row * D + tid * 4) = y;
}

// ---------------------------------------------------------------------------
extern "C" void kernel_launch(void* const* d_in, const int* in_sizes, int n_in,
                              void* d_out, int out_size)
{
    (void)in_sizes; (void)n_in;
    const float* Xq = (const float*)d_in[0];
    const float* Xk = (const float*)d_in[1];
    const float* Xv = (const float*)d_in[2];
    const unsigned char* mask = (const unsigned char*)d_in[3];
    const float* Wraw[4] = {(const float*)d_in[4], (const float*)d_in[5],
                            (const float*)d_in[6], (const float*)d_in[7]};
    const float* gam = (const float*)d_in[8];
    const float* bet = (const float*)d_in[9];
    float* out = (float*)d_out;

    bf16 *gW, *gQ, *gK, *gV, *gO;
    float *gY, *grs, *gfb;
    cudaGetSymbolAddress((void**)&gW, g_W);
    cudaGetSymbolAddress((void**)&gQ, g_Qs);
    cudaGetSymbolAddress((void**)&gK, g_Ks);
    cudaGetSymbolAddress((void**)&gV, g_Vs);
    cudaGetSymbolAddress((void**)&gO, g_Os);
    cudaGetSymbolAddress((void**)&gY, g_Y);
    cudaGetSymbolAddress((void**)&grs, g_rowsum);
    cudaGetSymbolAddress((void**)&gfb, g_attn_fb);
    const size_t DD = (size_t)D * D;
    const size_t TD = (size_t)MTOK * D;

    float* attnp = ((long long)out_size >= OUT_ELEMS + ATTN_ELEMS)
                       ? (out + OUT_ELEMS) : gfb;

    // 1) weight split (W -> W^T hi/lo bf16)
    for (int i = 0; i < 4; i++)
        wsplit_k<<<1024, 256>>>(Wraw[i], gW + (size_t)(2 * i) * DD,
                                gW + (size_t)(2 * i + 1) * DD);

    // 2) projections
    const dim3 gproj(4, 64);
    gemm_bs<0><<<gproj, 256>>>(Xq, nullptr, nullptr,
                               gW + 0 * DD, gW + 1 * DD,
                               gQ, gQ + TD, nullptr, nullptr);
    gemm_bs<0><<<gproj, 256>>>(Xk, nullptr, nullptr,
                               gW + 2 * DD, gW + 3 * DD,
                               gK, gK + TD, nullptr, nullptr);
    gemm_bs<0><<<gproj, 256>>>(Xv, nullptr, nullptr,
                               gW + 4 * DD, gW + 5 * DD,
                               gV, gV + TD, nullptr, nullptr);

    // 3) scores + softmax numerators
    cudaMemsetAsync(grs, 0, sizeof(float) * BH * S);
    scores_bs<<<dim3(16, 16, 32), 256>>>(gQ, gQ + TD, gK, gK + TD,
                                         mask, attnp, grs);
    // 4) normalize (finalizes attn output) + PV
    pv_bs<<<dim3(16, 32), 256>>>(attnp, gV, gV + TD, grs, gO, gO + TD);

    // 5) out proj + residual, then LayerNorm
    gemm_bs<2><<<gproj, 256>>>(nullptr, gO, gO + TD,
                               gW + 6 * DD, gW + 7 * DD,
                               nullptr, nullptr, Xq, gY);
    ln_k<<<MTOK, 128>>>(gY, gam, bet, out);
}

// round 12
// speedup vs baseline: 2.0616x; 2.0616x over previous
#include <cuda_runtime.h>
#include <cuda_bf16.h>
#include <cuda_fp16.h>
#include <cstdint>

// ---------------------------------------------------------------------------
// MHA block, tensor cores via mma.sync. Precision-tiered:
//   Q/K proj : bf16 split (3 MMA)  -> fp16 outputs
//   scores   : fp16 x fp16 (1 MMA) -> exp -> attn f32 (output #2) + rowsums
//   V proj   : bf16 single (1 MMA)
//   PV       : bf16 single (1 MMA), cp.async pipelined; O f32
//   out proj : bf16 single (1 MMA) + residual -> LayerNorm (output #1)
// R12 fix: pv_k smem STORES go through generic pointers (R11 dereferenced
// cvta'd shared-window u32 addresses -> illegal access).
// ---------------------------------------------------------------------------

using bf16 = __nv_bfloat16;
using f16  = __half;
typedef unsigned int u32;

namespace {
constexpr int B = 4, S = 2048, D = 512, H = 8, BH = 32, MTOK = 8192;
constexpr long long OUT_ELEMS  = (long long)MTOK * D;
constexpr long long ATTN_ELEMS = (long long)BH * S * (long long)S;

// gemm3 smem: 4 tiles of 128 rows x 80B
constexpr int G3_AH = 0, G3_AL = 10240, G3_BH = 20480, G3_BL = 30720;
constexpr int SM_G3 = 40960;
// gemm1 smem: 2 tiles
constexpr int G1_A = 0, G1_B = 10240, SM_G1 = 20480;
// scores smem: 2 fp16 tiles
constexpr int SC_Q = 0, SC_K = 10240, SM_SC = 20480;
// pv smem: P double buf (128x80B), V double buf (32x144B), rinv
constexpr int PV_P0 = 0, PV_P1 = 10240, PV_V0 = 20480, PV_V1 = 25088,
              PV_RI = 29696, SM_PV = 30208;
}

// ---- device scratch (allocation-free rule) ---------------------------------
__device__ bf16  g_Wq[2][(size_t)D * D];          // W_Q^T hi/lo
__device__ bf16  g_Wk[2][(size_t)D * D];          // W_K^T hi/lo
__device__ bf16  g_Wv[(size_t)D * D];             // W_V^T single
__device__ bf16  g_Wo[(size_t)D * D];             // W_O^T single
__device__ f16   g_Qh[(size_t)MTOK * D];
__device__ f16   g_Kh[(size_t)MTOK * D];
__device__ bf16  g_Vb[(size_t)MTOK * D];
__device__ float g_Of[(size_t)MTOK * D];
__device__ float g_Y[(size_t)MTOK * D];
__device__ float g_rowsum[BH * S];
__device__ float g_attn_fb[(size_t)BH * S * (size_t)S];

// ---- PTX helpers ------------------------------------------------------------
__device__ __forceinline__ u32 cvta_smem(const void* p) {
    u32 a;
    asm("{ .reg .u64 t; cvta.to.shared.u64 t, %1; cvt.u32.u64 %0, t; }"
        : "=r"(a) : "l"(p));
    return a;
}
__device__ __forceinline__ void ldsm4(u32& r0, u32& r1, u32& r2, u32& r3, u32 a) {
    asm volatile("ldmatrix.sync.aligned.m8n8.x4.shared.b16 {%0,%1,%2,%3}, [%4];"
                 : "=r"(r0), "=r"(r1), "=r"(r2), "=r"(r3) : "r"(a));
}
__device__ __forceinline__ void ldsm2(u32& r0, u32& r1, u32 a) {
    asm volatile("ldmatrix.sync.aligned.m8n8.x2.shared.b16 {%0,%1}, [%2];"
                 : "=r"(r0), "=r"(r1) : "r"(a));
}
__device__ __forceinline__ void ldsm2t(u32& r0, u32& r1, u32 a) {
    asm volatile("ldmatrix.sync.aligned.m8n8.x2.trans.shared.b16 {%0,%1}, [%2];"
                 : "=r"(r0), "=r"(r1) : "r"(a));
}
__device__ __forceinline__ void mma_bb(float* c, const u32* a, const u32* b) {
    asm volatile(
        "mma.sync.aligned.m16n8k16.row.col.f32.bf16.bf16.f32 "
        "{%0,%1,%2,%3}, {%4,%5,%6,%7}, {%8,%9}, {%0,%1,%2,%3};"
        : "+f"(c[0]), "+f"(c[1]), "+f"(c[2]), "+f"(c[3])
        : "r"(a[0]), "r"(a[1]), "r"(a[2]), "r"(a[3]), "r"(b[0]), "r"(b[1]));
}
__device__ __forceinline__ void mma_ff(float* c, const u32* a, const u32* b) {
    asm volatile(
        "mma.sync.aligned.m16n8k16.row.col.f32.f16.f16.f32 "
        "{%0,%1,%2,%3}, {%4,%5,%6,%7}, {%8,%9}, {%0,%1,%2,%3};"
        : "+f"(c[0]), "+f"(c[1]), "+f"(c[2]), "+f"(c[3])
        : "r"(a[0]), "r"(a[1]), "r"(a[2]), "r"(a[3]), "r"(b[0]), "r"(b[1]));
}
__device__ __forceinline__ void cp16(u32 dst, const void* src) {
    asm volatile("cp.async.cg.shared.global [%0], [%1], 16;"
                 :: "r"(dst), "l"(src));
}
__device__ __forceinline__ void cp_commit() {
    asm volatile("cp.async.commit_group;" ::: "memory");
}
__device__ __forceinline__ void cp_wait0() {
    asm volatile("cp.async.wait_group 0;" ::: "memory");
}

// ---- split / pack ------------------------------------------------------------
__device__ __forceinline__ void split1(float x, bf16& h, bf16& l) {
    h = __float2bfloat16(x);
    l = __float2bfloat16(x - __bfloat162float(h));
}
__device__ __forceinline__ u32 pack2(bf16 a, bf16 b) {
    return (u32)__bfloat16_as_ushort(a) | ((u32)__bfloat16_as_ushort(b) << 16);
}
__device__ __forceinline__ u32 pack2h(f16 a, f16 b) {
    return (u32)__half_as_ushort(a) | ((u32)__half_as_ushort(b) << 16);
}
__device__ __forceinline__ void split8(float4 v0, float4 v1, uint4& hi, uint4& lo) {
    bf16 ha, la, hb, lb;
    split1(v0.x, ha, la); split1(v0.y, hb, lb); hi.x = pack2(ha, hb); lo.x = pack2(la, lb);
    split1(v0.z, ha, la); split1(v0.w, hb, lb); hi.y = pack2(ha, hb); lo.y = pack2(la, lb);
    split1(v1.x, ha, la); split1(v1.y, hb, lb); hi.z = pack2(ha, hb); lo.z = pack2(la, lb);
    split1(v1.z, ha, la); split1(v1.w, hb, lb); hi.w = pack2(ha, hb); lo.w = pack2(la, lb);
}
__device__ __forceinline__ uint4 cvt8(float4 a, float4 b) {
    uint4 r;
    r.x = pack2(__float2bfloat16(a.x), __float2bfloat16(a.y));
    r.y = pack2(__float2bfloat16(a.z), __float2bfloat16(a.w));
    r.z = pack2(__float2bfloat16(b.x), __float2bfloat16(b.y));
    r.w = pack2(__float2bfloat16(b.z), __float2bfloat16(b.w));
    return r;
}

// ---------------------------------------------------------------------------
// Weight prep
// ---------------------------------------------------------------------------
__global__ void wsplit_k(const float* __restrict__ w,
                         bf16* __restrict__ hi, bf16* __restrict__ lo) {
    int i = blockIdx.x * 256 + threadIdx.x;
    int k = i >> 9, n = i & 511;
    bf16 h, l; split1(w[i], h, l);
    hi[(size_t)n * 512 + k] = h;
    lo[(size_t)n * 512 + k] = l;
}
__global__ void wsingle_k(const float* __restrict__ w, bf16* __restrict__ t) {
    int i = blockIdx.x * 256 + threadIdx.x;
    int k = i >> 9, n = i & 511;
    t[(size_t)n * 512 + k] = __float2bfloat16(w[i]);
}

// ---------------------------------------------------------------------------
// gemm3: split-bf16 (3 MMA) GEMM, K=512, A from f32, B bf16 pair -> fp16 C.
// ---------------------------------------------------------------------------
__global__ __launch_bounds__(256)
void gemm3_k(const float* __restrict__ Af,
             const bf16* __restrict__ Bhi, const bf16* __restrict__ Blo,
             f16* __restrict__ Ch)
{
    __shared__ __align__(16) char sm[SM_G3];
    const int tid = threadIdx.x, lane = tid & 31, wi = tid >> 5;
    const int m0 = blockIdx.y * 128, n0 = blockIdx.x * 128;
    const int m0w = (wi >> 2) * 64, n0w = (wi & 3) * 32;
    const u32 sb = cvta_smem(sm);
    const int r = tid >> 1, hf = tid & 1;
    const u32 soff = (u32)(r * 80 + hf * 32);
    const int la15 = lane & 15, lc = lane >> 4;
    const int l7 = lane & 7, lb = (lane >> 3) & 1;

    float acc[4][4][4];
#pragma unroll
    for (int i = 0; i < 4; i++)
#pragma unroll
        for (int j = 0; j < 4; j++)
#pragma unroll
            for (int q = 0; q < 4; q++) acc[i][j][q] = 0.f;

    for (int c = 0; c < 16; c++) {
        const int k0 = c * 32;
        {
            const float4* ap = (const float4*)(Af + (size_t)(m0 + r) * 512 + k0 + hf * 16);
            uint4 h0, l0, h1, l1;
            split8(ap[0], ap[1], h0, l0);
            split8(ap[2], ap[3], h1, l1);
            *(uint4*)(sm + G3_AH + soff)      = h0;
            *(uint4*)(sm + G3_AH + soff + 16) = h1;
            *(uint4*)(sm + G3_AL + soff)      = l0;
            *(uint4*)(sm + G3_AL + soff + 16) = l1;
        }
        {
            const uint4* ph = (const uint4*)(Bhi + (size_t)(n0 + r) * 512 + k0 + hf * 16);
            const uint4* pl = (const uint4*)(Blo + (size_t)(n0 + r) * 512 + k0 + hf * 16);
            *(uint4*)(sm + G3_BH + soff)      = ph[0];
            *(uint4*)(sm + G3_BH + soff + 16) = ph[1];
            *(uint4*)(sm + G3_BL + soff)      = pl[0];
            *(uint4*)(sm + G3_BL + soff + 16) = pl[1];
        }
        __syncthreads();
#pragma unroll
        for (int ks = 0; ks < 2; ks++) {
            const u32 ko = (u32)(ks * 32);
            u32 ah[4][4], al[4][4];
#pragma unroll
            for (int mt = 0; mt < 4; mt++) {
                u32 a = sb + G3_AH + (u32)((m0w + mt * 16 + la15) * 80) + ko + lc * 16;
                ldsm4(ah[mt][0], ah[mt][1], ah[mt][2], ah[mt][3], a);
                ldsm4(al[mt][0], al[mt][1], al[mt][2], al[mt][3], a + (G3_AL - G3_AH));
            }
            u32 bh_[4][2], bl_[4][2];
#pragma unroll
            for (int nt = 0; nt < 4; nt++) {
                u32 a = sb + G3_BH + (u32)((n0w + nt * 8 + l7) * 80) + ko + lb * 16;
                ldsm2(bh_[nt][0], bh_[nt][1], a);
                ldsm2(bl_[nt][0], bl_[nt][1], a + (G3_BL - G3_BH));
            }
#pragma unroll
            for (int mt = 0; mt < 4; mt++)
#pragma unroll
                for (int nt = 0; nt < 4; nt++) {
                    mma_bb(acc[mt][nt], ah[mt], bh_[nt]);
                    mma_bb(acc[mt][nt], ah[mt], bl_[nt]);
                    mma_bb(acc[mt][nt], al[mt], bh_[nt]);
                }
        }
        __syncthreads();
    }

    const int g = lane >> 2, tg = lane & 3;
#pragma unroll
    for (int mt = 0; mt < 4; mt++)
#pragma unroll
        for (int h2 = 0; h2 < 2; h2++) {
            const size_t m = (size_t)(m0 + m0w + mt * 16 + h2 * 8 + g);
#pragma unroll
            for (int nt = 0; nt < 4; nt++) {
                const int ncol = n0 + n0w + nt * 8 + tg * 2;
                *(u32*)(Ch + m * 512 + ncol) =
                    pack2h(__float2half(acc[mt][nt][h2 * 2]),
                           __float2half(acc[mt][nt][h2 * 2 + 1]));
            }
        }
}

// ---------------------------------------------------------------------------
// gemm1: single-bf16 GEMM (1 MMA), K=512, A from f32, B bf16 single.
// EPI 0: C -> bf16 (V projection).  EPI 1: C + R -> f32 Yf (out proj).
// ---------------------------------------------------------------------------
template<int EPI>
__global__ __launch_bounds__(256)
void gemm1_k(const float* __restrict__ Af, const bf16* __restrict__ Bs,
             bf16* __restrict__ Cb, const float* __restrict__ R,
             float* __restrict__ Yf)
{
    __shared__ __align__(16) char sm[SM_G1];
    const int tid = threadIdx.x, lane = tid & 31, wi = tid >> 5;
    const int m0 = blockIdx.y * 128, n0 = blockIdx.x * 128;
    const int m0w = (wi >> 2) * 64, n0w = (wi & 3) * 32;
    const u32 sb = cvta_smem(sm);
    const int r = tid >> 1, hf = tid & 1;
    const u32 soff = (u32)(r * 80 + hf * 32);
    const int la15 = lane & 15, lc = lane >> 4;
    const int l7 = lane & 7, lb = (lane >> 3) & 1;

    float acc[4][4][4];
#pragma unroll
    for (int i = 0; i < 4; i++)
#pragma unroll
        for (int j = 0; j < 4; j++)
#pragma unroll
            for (int q = 0; q < 4; q++) acc[i][j][q] = 0.f;

    for (int c = 0; c < 16; c++) {
        const int k0 = c * 32;
        {
            const float4* ap = (const float4*)(Af + (size_t)(m0 + r) * 512 + k0 + hf * 16);
            *(uint4*)(sm + G1_A + soff)      = cvt8(ap[0], ap[1]);
            *(uint4*)(sm + G1_A + soff + 16) = cvt8(ap[2], ap[3]);
        }
        {
            const uint4* bp = (const uint4*)(Bs + (size_t)(n0 + r) * 512 + k0 + hf * 16);
            *(uint4*)(sm + G1_B + soff)      = bp[0];
            *(uint4*)(sm + G1_B + soff + 16) = bp[1];
        }
        __syncthreads();
#pragma unroll
        for (int ks = 0; ks < 2; ks++) {
            const u32 ko = (u32)(ks * 32);
            u32 a4[4][4];
#pragma unroll
            for (int mt = 0; mt < 4; mt++) {
                u32 a = sb + G1_A + (u32)((m0w + mt * 16 + la15) * 80) + ko + lc * 16;
                ldsm4(a4[mt][0], a4[mt][1], a4[mt][2], a4[mt][3], a);
            }
            u32 b2[4][2];
#pragma unroll
            for (int nt = 0; nt < 4; nt++) {
                u32 a = sb + G1_B + (u32)((n0w + nt * 8 + l7) * 80) + ko + lb * 16;
                ldsm2(b2[nt][0], b2[nt][1], a);
            }
#pragma unroll
            for (int mt = 0; mt < 4; mt++)
#pragma unroll
                for (int nt = 0; nt < 4; nt++)
                    mma_bb(acc[mt][nt], a4[mt], b2[nt]);
        }
        __syncthreads();
    }

    const int g = lane >> 2, tg = lane & 3;
#pragma unroll
    for (int mt = 0; mt < 4; mt++)
#pragma unroll
        for (int h2 = 0; h2 < 2; h2++) {
            const size_t m = (size_t)(m0 + m0w + mt * 16 + h2 * 8 + g);
#pragma unroll
            for (int nt = 0; nt < 4; nt++) {
                const int ncol = n0 + n0w + nt * 8 + tg * 2;
                const float x0 = acc[mt][nt][h2 * 2], x1 = acc[mt][nt][h2 * 2 + 1];
                if (EPI == 0) {
                    *(u32*)(Cb + m * 512 + ncol) =
                        pack2(__float2bfloat16(x0), __float2bfloat16(x1));
                } else {
                    const float2 rv = *(const float2*)(R + m * 512 + ncol);
                    *(float2*)(Yf + m * 512 + ncol) = make_float2(x0 + rv.x, x1 + rv.y);
                }
            }
        }
}

// ---------------------------------------------------------------------------
// Scores: fp16 x fp16 (1 MMA). exp -> attn f32 (unnormalized) + rowsums.
// One CTA = 128q x 128k of one (b,h); DK=64 = two BK=32 stages.
// ---------------------------------------------------------------------------
__global__ __launch_bounds__(256)
void scores_k(const f16* __restrict__ Qh, const f16* __restrict__ Kh,
              const unsigned char* __restrict__ mask,
              float* __restrict__ attn, float* __restrict__ rowsum)
{
    __shared__ __align__(16) char sm[SM_SC];
    const int tid = threadIdx.x, lane = tid & 31, wi = tid >> 5;
    const int bh = blockIdx.z, b_ = bh >> 3, h_ = bh & 7;
    const int q0 = blockIdx.y * 128, kt0 = blockIdx.x * 128;
    const int m0w = (wi >> 2) * 64, n0w = (wi & 3) * 32;
    const u32 sb = cvta_smem(sm);
    const int r = tid >> 1, hf = tid & 1;
    const u32 soff = (u32)(r * 80 + hf * 32);
    const int la15 = lane & 15, lc = lane >> 4;
    const int l7 = lane & 7, lb = (lane >> 3) & 1;

    float acc[4][4][4];
#pragma unroll
    for (int i = 0; i < 4; i++)
#pragma unroll
        for (int j = 0; j < 4; j++)
#pragma unroll
            for (int q = 0; q < 4; q++) acc[i][j][q] = 0.f;

#pragma unroll
    for (int c = 0; c < 2; c++) {
        const int k0 = h_ * 64 + c * 32;
        {
            const uint4* qp = (const uint4*)(Qh + (size_t)(b_ * S + q0 + r) * 512 + k0 + hf * 16);
            *(uint4*)(sm + SC_Q + soff)      = qp[0];
            *(uint4*)(sm + SC_Q + soff + 16) = qp[1];
        }
        {
            const uint4* kp = (const uint4*)(Kh + (size_t)(b_ * S + kt0 + r) * 512 + k0 + hf * 16);
            *(uint4*)(sm + SC_K + soff)      = kp[0];
            *(uint4*)(sm + SC_K + soff + 16) = kp[1];
        }
        __syncthreads();
#pragma unroll
        for (int ks = 0; ks < 2; ks++) {
            const u32 ko = (u32)(ks * 32);
            u32 a4[4][4];
#pragma unroll
            for (int mt = 0; mt < 4; mt++) {
                u32 a = sb + SC_Q + (u32)((m0w + mt * 16 + la15) * 80) + ko + lc * 16;
                ldsm4(a4[mt][0], a4[mt][1], a4[mt][2], a4[mt][3], a);
            }
            u32 b2[4][2];
#pragma unroll
            for (int nt = 0; nt < 4; nt++) {
                u32 a = sb + SC_K + (u32)((n0w + nt * 8 + l7) * 80) + ko + lb * 16;
                ldsm2(b2[nt][0], b2[nt][1], a);
            }
#pragma unroll
            for (int mt = 0; mt < 4; mt++)
#pragma unroll
                for (int nt = 0; nt < 4; nt++)
                    mma_ff(acc[mt][nt], a4[mt], b2[nt]);
        }
        __syncthreads();
    }

    const int g = lane >> 2, tg = lane & 3;
#pragma unroll
    for (int mt = 0; mt < 4; mt++)
#pragma unroll
        for (int h2 = 0; h2 < 2; h2++) {
            const int q = q0 + m0w + mt * 16 + h2 * 8 + g;
            const unsigned char* mrow = mask + (size_t)(b_ * S + q) * S + kt0;
            float* arow = attn + ((size_t)bh * S + q) * S + kt0;
            float rs = 0.f;
#pragma unroll
            for (int nt = 0; nt < 4; nt++) {
                const int col = n0w + nt * 8 + tg * 2;
                const unsigned short mv = *(const unsigned short*)(mrow + col);
                const float e0 = (mv & 0xff) ? 0.f : __expf(acc[mt][nt][h2 * 2]     * 0.125f);
                const float e1 = (mv >> 8)   ? 0.f : __expf(acc[mt][nt][h2 * 2 + 1] * 0.125f);
                *(float2*)(arow + col) = make_float2(e0, e1);
                rs += e0 + e1;
            }
            rs += __shfl_xor_sync(0xffffffffu, rs, 1);
            rs += __shfl_xor_sync(0xffffffffu, rs, 2);
            if (tg == 0) atomicAdd(&rowsum[(size_t)bh * S + q], rs);
        }
}

// ---------------------------------------------------------------------------
// PV: normalize attn in place (final output #2) and O = P @ V (1 MMA).
// cp.async double-buffered V, register-staged P. O -> f32.
// ---------------------------------------------------------------------------
__global__ __launch_bounds__(256)
void pv_k(float* __restrict__ attn, const bf16* __restrict__ Vb,
          const float* __restrict__ rowsum, float* __restrict__ O)
{
    __shared__ __align__(16) char sm[SM_PV];
    const int tid = threadIdx.x, lane = tid & 31, wi = tid >> 5;
    const int bh = blockIdx.y, b_ = bh >> 3, h_ = bh & 7;
    const int q0 = blockIdx.x * 128;
    const int m0w = (wi >> 1) * 32, n0w = (wi & 1) * 32;
    const u32 sb = cvta_smem(sm);
    float* rinv_s = (float*)(sm + PV_RI);
    if (tid < 128) rinv_s[tid] = 1.0f / rowsum[(size_t)bh * S + q0 + tid];
    __syncthreads();

    const int r = tid >> 1, hf = tid & 1;
    const u32 soff = (u32)(r * 80 + hf * 32);
    const int vr = tid >> 3, vc = tid & 7;
    float* arow = attn + ((size_t)bh * S + q0 + r) * S + hf * 16;
    const float rv = rinv_s[r];
    const int la15 = lane & 15, lc = lane >> 4;
    // u32 shared-window addrs for PTX ops; generic char* for C++ stores
    const u32 pbu[2] = {sb + PV_P0, sb + PV_P1};
    const u32 vbu[2] = {sb + PV_V0, sb + PV_V1};
    char* const pbc[2] = {sm + PV_P0, sm + PV_P1};

    float acc[2][4][4];
#pragma unroll
    for (int i = 0; i < 2; i++)
#pragma unroll
        for (int j = 0; j < 4; j++)
#pragma unroll
            for (int q = 0; q < 4; q++) acc[i][j][q] = 0.f;

    float4 pr[4];
    // prologue: stage chunk 0 into buffer 0
    {
        cp16(vbu[0] + (u32)(vr * 144 + vc * 16),
             Vb + (size_t)(b_ * S + vr) * 512 + h_ * 64 + vc * 8);
        cp_commit();
        float4* gp = (float4*)arow;
#pragma unroll
        for (int i = 0; i < 4; i++) pr[i] = gp[i];
#pragma unroll
        for (int i = 0; i < 4; i++) {
            pr[i].x *= rv; pr[i].y *= rv; pr[i].z *= rv; pr[i].w *= rv;
            gp[i] = pr[i];
        }
        *(uint4*)(pbc[0] + soff)      = cvt8(pr[0], pr[1]);
        *(uint4*)(pbc[0] + soff + 16) = cvt8(pr[2], pr[3]);
        cp_wait0();
        __syncthreads();
    }

    for (int c = 0; c < 64; c++) {
        const int cur = c & 1, nxt = cur ^ 1;
        const int ktn = (c + 1) * 32;
        if (c < 63) {   // issue next-chunk loads early (latency hidden by MMA)
            cp16(vbu[nxt] + (u32)(vr * 144 + vc * 16),
                 Vb + (size_t)(b_ * S + ktn + vr) * 512 + h_ * 64 + vc * 8);
            cp_commit();
            float4* gp = (float4*)(arow + ktn);
#pragma unroll
            for (int i = 0; i < 4; i++) pr[i] = gp[i];
        }
        // compute on current buffers
#pragma unroll
        for (int ks = 0; ks < 2; ks++) {
            const u32 ko = (u32)(ks * 32);
            u32 a4[2][4];
#pragma unroll
            for (int mt = 0; mt < 2; mt++) {
                u32 a = pbu[cur] + (u32)((m0w + mt * 16 + la15) * 80) + ko + lc * 16;
                ldsm4(a4[mt][0], a4[mt][1], a4[mt][2], a4[mt][3], a);
            }
            u32 b2[4][2];
#pragma unroll
            for (int nt = 0; nt < 4; nt++) {
                u32 a = vbu[cur] + (u32)((ks * 16 + la15) * 144 + (n0w + nt * 8) * 2);
                ldsm2t(b2[nt][0], b2[nt][1], a);
            }
#pragma unroll
            for (int mt = 0; mt < 2; mt++)
#pragma unroll
                for (int nt = 0; nt < 4; nt++)
                    mma_bb(acc[mt][nt], a4[mt], b2[nt]);
        }
        if (c < 63) {   // normalize next chunk, finalize attn, stage to smem
            float4* gp = (float4*)(arow + ktn);
#pragma unroll
            for (int i = 0; i < 4; i++) {
                pr[i].x *= rv; pr[i].y *= rv; pr[i].z *= rv; pr[i].w *= rv;
                gp[i] = pr[i];
            }
            *(uint4*)(pbc[nxt] + soff)      = cvt8(pr[0], pr[1]);
            *(uint4*)(pbc[nxt] + soff + 16) = cvt8(pr[2], pr[3]);
        }
        cp_wait0();
        __syncthreads();
    }

    const int g = lane >> 2, tg = lane & 3;
#pragma unroll
    for (int mt = 0; mt < 2; mt++)
#pragma unroll
        for (int h2 = 0; h2 < 2; h2++) {
            const size_t m = (size_t)(b_ * S + q0 + m0w + mt * 16 + h2 * 8 + g);
#pragma unroll
            for (int nt = 0; nt < 4; nt++) {
                const int ncol = h_ * 64 + n0w + nt * 8 + tg * 2;
                *(float2*)(O + m * 512 + ncol) =
                    make_float2(acc[mt][nt][h2 * 2], acc[mt][nt][h2 * 2 + 1]);
            }
        }
}

// ---------------------------------------------------------------------------
// Row LayerNorm: 1 block (128 threads) per row of 512.
// ---------------------------------------------------------------------------
__global__ __launch_bounds__(128)
void ln_k(const float* __restrict__ X, const float* __restrict__ gam,
          const float* __restrict__ bet, float* __restrict__ out)
{
    __shared__ float red[4];
    const int row = blockIdx.x, tid = threadIdx.x;
    const int lane = tid & 31, wid = tid >> 5;
    const float4 x = *(const float4*)(X + (size_t)row * D + tid * 4);

    float s = x.x + x.y + x.z + x.w;
#pragma unroll
    for (int off = 16; off > 0; off >>= 1) s += __shfl_xor_sync(~0u, s, off);
    if (lane == 0) red[wid] = s;
    __syncthreads();
    const float mu = (red[0] + red[1] + red[2] + red[3]) * (1.0f / D);
    __syncthreads();

    const float4 dx = make_float4(x.x - mu, x.y - mu, x.z - mu, x.w - mu);
    float q = dx.x * dx.x + dx.y * dx.y + dx.z * dx.z + dx.w * dx.w;
#pragma unroll
    for (int off = 16; off > 0; off >>= 1) q += __shfl_xor_sync(~0u, q, off);
    if (lane == 0) red[wid] = q;
    __syncthreads();
    const float var = (red[0] + red[1] + red[2] + red[3]) * (1.0f / D);
    const float inv = rsqrtf(var + 1e-5f);

    const float4 g  = *(const float4*)(gam + tid * 4);
    const float4 bb = *(const float4*)(bet + tid * 4);
    float4 y;
    y.x = dx.x * inv * g.x + bb.x;
    y.y = dx.y * inv * g.y + bb.y;
    y.z = dx.z * inv * g.z + bb.z;
    y.w = dx.w * inv * g.w + bb.w;
    *(float4*)(out + (size_t)row * D + tid * 4) = y;
}

// ---------------------------------------------------------------------------
extern "C" void kernel_launch(void* const* d_in, const int* in_sizes, int n_in,
                              void* d_out, int out_size)
{
    (void)in_sizes; (void)n_in;
    const float* Xq = (const float*)d_in[0];
    const float* Xk = (const float*)d_in[1];
    const float* Xv = (const float*)d_in[2];
    const unsigned char* mask = (const unsigned char*)d_in[3];
    const float* Wq = (const float*)d_in[4];
    const float* Wk = (const float*)d_in[5];
    const float* Wv = (const float*)d_in[6];
    const float* Wo = (const float*)d_in[7];
    const float* gam = (const float*)d_in[8];
    const float* bet = (const float*)d_in[9];
    float* out = (float*)d_out;

    bf16 *gWq, *gWk, *gWv, *gWo, *gVb;
    f16 *gQh, *gKh;
    float *gOf, *gY, *grs, *gfb;
    cudaGetSymbolAddress((void**)&gWq, g_Wq);
    cudaGetSymbolAddress((void**)&gWk, g_Wk);
    cudaGetSymbolAddress((void**)&gWv, g_Wv);
    cudaGetSymbolAddress((void**)&gWo, g_Wo);
    cudaGetSymbolAddress((void**)&gQh, g_Qh);
    cudaGetSymbolAddress((void**)&gKh, g_Kh);
    cudaGetSymbolAddress((void**)&gVb, g_Vb);
    cudaGetSymbolAddress((void**)&gOf, g_Of);
    cudaGetSymbolAddress((void**)&gY, g_Y);
    cudaGetSymbolAddress((void**)&grs, g_rowsum);
    cudaGetSymbolAddress((void**)&gfb, g_attn_fb);
    const size_t DD = (size_t)D * D;

    float* attnp = ((long long)out_size >= OUT_ELEMS + ATTN_ELEMS)
                       ? (out + OUT_ELEMS) : gfb;

    // 1) weight prep
    wsplit_k<<<1024, 256>>>(Wq, gWq, gWq + DD);
    wsplit_k<<<1024, 256>>>(Wk, gWk, gWk + DD);
    wsingle_k<<<1024, 256>>>(Wv, gWv);
    wsingle_k<<<1024, 256>>>(Wo, gWo);

    // 2) projections
    const dim3 gproj(4, 64);
    gemm3_k<<<gproj, 256>>>(Xq, gWq, gWq + DD, gQh);
    gemm3_k<<<gproj, 256>>>(Xk, gWk, gWk + DD, gKh);
    gemm1_k<0><<<gproj, 256>>>(Xv, gWv, gVb, nullptr, nullptr);

    // 3) scores + softmax numerators
    cudaMemsetAsync(grs, 0, sizeof(float) * BH * S);
    scores_k<<<dim3(16, 16, 32), 256>>>(gQh, gKh, mask, attnp, grs);

    // 4) normalize (finalizes attn output) + PV -> O f32
    pv_k<<<dim3(16, 32), 256>>>(attnp, gVb, grs, gOf);

    // 5) out proj + residual, then LayerNorm
    gemm1_k<1><<<gproj, 256>>>(gOf, gWo, nullptr, Xq, gY);
    ln_k<<<MTOK, 128>>>(gY, gam, bet, out);
}

// round 13
// speedup vs baseline: 2.1276x; 1.0320x over previous
#include <cuda_runtime.h>
#include <cuda_bf16.h>
#include <cuda_fp16.h>
#include <cstdint>

// ---------------------------------------------------------------------------
// MHA block, mma.sync tensor cores, precision-tiered (R12 scheme) +
// R13: cp.async double-buffered GEMM pipelines, batched Q/K projection,
// all GEMM operands pre-converted to bf16 so loads are raw cp.async.
// ---------------------------------------------------------------------------

using bf16 = __nv_bfloat16;
using f16  = __half;
typedef unsigned int u32;

namespace {
constexpr int B = 4, S = 2048, D = 512, H = 8, BH = 32, MTOK = 8192;
constexpr long long OUT_ELEMS  = (long long)MTOK * D;
constexpr long long ATTN_ELEMS = (long long)BH * S * (long long)S;

// tile = 128 rows x 32 bf16 cols, 80B pitch -> 10240 B
constexpr int TILE = 10240;
// gemm3: 4 tiles/buffer x 2 buffers (dynamic smem)
constexpr int G3_BUF = 4 * TILE;            // 40960
constexpr int SM_G3  = 2 * G3_BUF;          // 81920
// gemm1: 2 tiles/buffer x 2 buffers (static)
constexpr int G1_BUF = 2 * TILE;            // 20480
constexpr int SM_G1  = 2 * G1_BUF;          // 40960
// scores smem: 2 fp16 tiles
constexpr int SC_Q = 0, SC_K = TILE, SM_SC = 2 * TILE;
// pv smem: P double buf, V double buf, rinv
constexpr int PV_P0 = 0, PV_P1 = TILE, PV_V0 = 2 * TILE, PV_V1 = 25088,
              PV_RI = 29696, SM_PV = 30208;
}

// ---- device scratch ----------------------------------------------------------
__device__ bf16  g_Wq[2][(size_t)D * D];
__device__ bf16  g_Wk[2][(size_t)D * D];
__device__ bf16  g_Wv[(size_t)D * D];
__device__ bf16  g_Wo[(size_t)D * D];
__device__ bf16  g_Xq[2][(size_t)MTOK * D];   // Xq split hi/lo
__device__ bf16  g_Xk[2][(size_t)MTOK * D];   // Xk split hi/lo
__device__ bf16  g_Xv[(size_t)MTOK * D];      // Xv single
__device__ f16   g_Qh[(size_t)MTOK * D];
__device__ f16   g_Kh[(size_t)MTOK * D];
__device__ bf16  g_Vb[(size_t)MTOK * D];
__device__ bf16  g_Ob[(size_t)MTOK * D];
__device__ float g_Y[(size_t)MTOK * D];
__device__ float g_rowsum[BH * S];
__device__ float g_attn_fb[(size_t)BH * S * (size_t)S];

// ---- PTX helpers ---------------------------------------------------------------
__device__ __forceinline__ u32 cvta_smem(const void* p) {
    u32 a;
    asm("{ .reg .u64 t; cvta.to.shared.u64 t, %1; cvt.u32.u64 %0, t; }"
        : "=r"(a) : "l"(p));
    return a;
}
__device__ __forceinline__ void ldsm4(u32& r0, u32& r1, u32& r2, u32& r3, u32 a) {
    asm volatile("ldmatrix.sync.aligned.m8n8.x4.shared.b16 {%0,%1,%2,%3}, [%4];"
                 : "=r"(r0), "=r"(r1), "=r"(r2), "=r"(r3) : "r"(a));
}
__device__ __forceinline__ void ldsm2(u32& r0, u32& r1, u32 a) {
    asm volatile("ldmatrix.sync.aligned.m8n8.x2.shared.b16 {%0,%1}, [%2];"
                 : "=r"(r0), "=r"(r1) : "r"(a));
}
__device__ __forceinline__ void ldsm2t(u32& r0, u32& r1, u32 a) {
    asm volatile("ldmatrix.sync.aligned.m8n8.x2.trans.shared.b16 {%0,%1}, [%2];"
                 : "=r"(r0), "=r"(r1) : "r"(a));
}
__device__ __forceinline__ void mma_bb(float* c, const u32* a, const u32* b) {
    asm volatile(
        "mma.sync.aligned.m16n8k16.row.col.f32.bf16.bf16.f32 "
        "{%0,%1,%2,%3}, {%4,%5,%6,%7}, {%8,%9}, {%0,%1,%2,%3};"
        : "+f"(c[0]), "+f"(c[1]), "+f"(c[2]), "+f"(c[3])
        : "r"(a[0]), "r"(a[1]), "r"(a[2]), "r"(a[3]), "r"(b[0]), "r"(b[1]));
}
__device__ __forceinline__ void mma_ff(float* c, const u32* a, const u32* b) {
    asm volatile(
        "mma.sync.aligned.m16n8k16.row.col.f32.f16.f16.f32 "
        "{%0,%1,%2,%3}, {%4,%5,%6,%7}, {%8,%9}, {%0,%1,%2,%3};"
        : "+f"(c[0]), "+f"(c[1]), "+f"(c[2]), "+f"(c[3])
        : "r"(a[0]), "r"(a[1]), "r"(a[2]), "r"(a[3]), "r"(b[0]), "r"(b[1]));
}
__device__ __forceinline__ void cp16(u32 dst, const void* src) {
    asm volatile("cp.async.cg.shared.global [%0], [%1], 16;" :: "r"(dst), "l"(src));
}
__device__ __forceinline__ void cp_commit() {
    asm volatile("cp.async.commit_group;" ::: "memory");
}
__device__ __forceinline__ void cp_wait0() {
    asm volatile("cp.async.wait_group 0;" ::: "memory");
}
__device__ __forceinline__ void cp_wait1() {
    asm volatile("cp.async.wait_group 1;" ::: "memory");
}

// ---- split / pack ----------------------------------------------------------------
__device__ __forceinline__ void split1(float x, bf16& h, bf16& l) {
    h = __float2bfloat16(x);
    l = __float2bfloat16(x - __bfloat162float(h));
}
__device__ __forceinline__ u32 pack2(bf16 a, bf16 b) {
    return (u32)__bfloat16_as_ushort(a) | ((u32)__bfloat16_as_ushort(b) << 16);
}
__device__ __forceinline__ u32 pack2h(f16 a, f16 b) {
    return (u32)__half_as_ushort(a) | ((u32)__half_as_ushort(b) << 16);
}
__device__ __forceinline__ uint4 cvt8(float4 a, float4 b) {
    uint4 r;
    r.x = pack2(__float2bfloat16(a.x), __float2bfloat16(a.y));
    r.y = pack2(__float2bfloat16(a.z), __float2bfloat16(a.w));
    r.z = pack2(__float2bfloat16(b.x), __float2bfloat16(b.y));
    r.w = pack2(__float2bfloat16(b.z), __float2bfloat16(b.w));
    return r;
}

// ---------------------------------------------------------------------------
// Prep kernels (batched via blockIdx.z)
// ---------------------------------------------------------------------------
__global__ void wsplit2_k(const float* __restrict__ wq, const float* __restrict__ wk,
                          bf16* __restrict__ oq, bf16* __restrict__ ok) {
    const float* w = blockIdx.z ? wk : wq;
    bf16* o = blockIdx.z ? ok : oq;
    int i = blockIdx.x * 256 + threadIdx.x;
    int k = i >> 9, n = i & 511;
    bf16 h, l; split1(w[i], h, l);
    o[(size_t)n * 512 + k] = h;                          // hi plane
    o[(size_t)D * D + (size_t)n * 512 + k] = l;          // lo plane
}
__global__ void wsingle2_k(const float* __restrict__ wv, const float* __restrict__ wo,
                           bf16* __restrict__ ov, bf16* __restrict__ oo) {
    const float* w = blockIdx.z ? wo : wv;
    bf16* o = blockIdx.z ? oo : ov;
    int i = blockIdx.x * 256 + threadIdx.x;
    int k = i >> 9, n = i & 511;
    o[(size_t)n * 512 + k] = __float2bfloat16(w[i]);
}
__global__ void xsplit2_k(const float* __restrict__ x0, const float* __restrict__ x1,
                          bf16* __restrict__ o0, bf16* __restrict__ o1) {
    const float* x = blockIdx.z ? x1 : x0;
    bf16* o = blockIdx.z ? o1 : o0;
    const size_t i = ((size_t)blockIdx.x * 256 + threadIdx.x) * 4;
    float4 v = *(const float4*)(x + i);
    bf16 h0, l0, h1, l1, h2, l2, h3, l3;
    split1(v.x, h0, l0); split1(v.y, h1, l1);
    split1(v.z, h2, l2); split1(v.w, h3, l3);
    *(uint2*)(o + i) = make_uint2(pack2(h0, h1), pack2(h2, h3));
    *(uint2*)(o + (size_t)MTOK * D + i) = make_uint2(pack2(l0, l1), pack2(l2, l3));
}
__global__ void xsingle_k(const float* __restrict__ x, bf16* __restrict__ o) {
    const size_t i = ((size_t)blockIdx.x * 256 + threadIdx.x) * 4;
    float4 v = *(const float4*)(x + i);
    *(uint2*)(o + i) = make_uint2(
        pack2(__float2bfloat16(v.x), __float2bfloat16(v.y)),
        pack2(__float2bfloat16(v.z), __float2bfloat16(v.w)));
}

// ---------------------------------------------------------------------------
// Shared compute helpers (one BK=32 stage)
// ---------------------------------------------------------------------------
__device__ __forceinline__ void compute3_44(float acc[4][4][4], u32 sbuf,
                                            int m0w, int n0w, int lane)
{
    const int la15 = lane & 15, lc = lane >> 4;
    const int l7 = lane & 7, lb = (lane >> 3) & 1;
#pragma unroll
    for (int ks = 0; ks < 2; ks++) {
        const u32 ko = (u32)(ks * 32);
        u32 ah[4][4], al[4][4];
#pragma unroll
        for (int mt = 0; mt < 4; mt++) {
            u32 a = sbuf + (u32)((m0w + mt * 16 + la15) * 80) + ko + lc * 16;
            ldsm4(ah[mt][0], ah[mt][1], ah[mt][2], ah[mt][3], a);
            ldsm4(al[mt][0], al[mt][1], al[mt][2], al[mt][3], a + TILE);
        }
        u32 bh_[4][2], bl_[4][2];
#pragma unroll
        for (int nt = 0; nt < 4; nt++) {
            u32 a = sbuf + 2 * TILE + (u32)((n0w + nt * 8 + l7) * 80) + ko + lb * 16;
            ldsm2(bh_[nt][0], bh_[nt][1], a);
            ldsm2(bl_[nt][0], bl_[nt][1], a + TILE);
        }
#pragma unroll
        for (int mt = 0; mt < 4; mt++)
#pragma unroll
            for (int nt = 0; nt < 4; nt++) {
                mma_bb(acc[mt][nt], ah[mt], bh_[nt]);
                mma_bb(acc[mt][nt], ah[mt], bl_[nt]);
                mma_bb(acc[mt][nt], al[mt], bh_[nt]);
            }
    }
}
__device__ __forceinline__ void compute1_44(float acc[4][4][4], u32 sbuf,
                                            int m0w, int n0w, int lane)
{
    const int la15 = lane & 15, lc = lane >> 4;
    const int l7 = lane & 7, lb = (lane >> 3) & 1;
#pragma unroll
    for (int ks = 0; ks < 2; ks++) {
        const u32 ko = (u32)(ks * 32);
        u32 a4[4][4];
#pragma unroll
        for (int mt = 0; mt < 4; mt++) {
            u32 a = sbuf + (u32)((m0w + mt * 16 + la15) * 80) + ko + lc * 16;
            ldsm4(a4[mt][0], a4[mt][1], a4[mt][2], a4[mt][3], a);
        }
        u32 b2[4][2];
#pragma unroll
        for (int nt = 0; nt < 4; nt++) {
            u32 a = sbuf + TILE + (u32)((n0w + nt * 8 + l7) * 80) + ko + lb * 16;
            ldsm2(b2[nt][0], b2[nt][1], a);
        }
#pragma unroll
        for (int mt = 0; mt < 4; mt++)
#pragma unroll
            for (int nt = 0; nt < 4; nt++)
                mma_bb(acc[mt][nt], a4[mt], b2[nt]);
    }
}

// ---------------------------------------------------------------------------
// gemm3: split-bf16 (3 MMA), K=512, cp.async double-buffered, batched z=2
// (Q and K projections). Output fp16.
// ---------------------------------------------------------------------------
__global__ __launch_bounds__(256)
void gemm3_k(const bf16* __restrict__ A0, const bf16* __restrict__ B0,
             f16* __restrict__ C0,
             const bf16* __restrict__ A1, const bf16* __restrict__ B1,
             f16* __restrict__ C1)
{
    extern __shared__ __align__(16) char sm[];
    const bf16* A = blockIdx.z ? A1 : A0;        // hi plane; lo at +MTOK*D
    const bf16* Bw = blockIdx.z ? B1 : B0;       // hi plane; lo at +D*D
    f16* C = blockIdx.z ? C1 : C0;
    const size_t ALO = (size_t)MTOK * D, BLO = (size_t)D * D;

    const int tid = threadIdx.x, lane = tid & 31, wi = tid >> 5;
    const int m0 = blockIdx.y * 128, n0 = blockIdx.x * 128;
    const int m0w = (wi >> 2) * 64, n0w = (wi & 3) * 32;
    const u32 sb = cvta_smem(sm);
    const int r = tid >> 1, hf = tid & 1;
    const u32 soff = (u32)(r * 80 + hf * 32);

    float acc[4][4][4];
#pragma unroll
    for (int i = 0; i < 4; i++)
#pragma unroll
        for (int j = 0; j < 4; j++)
#pragma unroll
            for (int q = 0; q < 4; q++) acc[i][j][q] = 0.f;

    auto load_stage = [&](int c, u32 sbuf) {
        const size_t ao = (size_t)(m0 + r) * 512 + c * 32 + hf * 16;
        const size_t bo = (size_t)(n0 + r) * 512 + c * 32 + hf * 16;
        cp16(sbuf + soff,                 A + ao);
        cp16(sbuf + soff + 16,            A + ao + 8);
        cp16(sbuf + TILE + soff,          A + ALO + ao);
        cp16(sbuf + TILE + soff + 16,     A + ALO + ao + 8);
        cp16(sbuf + 2 * TILE + soff,      Bw + bo);
        cp16(sbuf + 2 * TILE + soff + 16, Bw + bo + 8);
        cp16(sbuf + 3 * TILE + soff,      Bw + BLO + bo);
        cp16(sbuf + 3 * TILE + soff + 16, Bw + BLO + bo + 8);
    };

    load_stage(0, sb);
    cp_commit();
    for (int c = 0; c < 16; c++) {
        const u32 cur = sb + (u32)((c & 1) * G3_BUF);
        if (c + 1 < 16) {
            load_stage(c + 1, sb + (u32)(((c + 1) & 1) * G3_BUF));
            cp_commit();
            cp_wait1();
        } else {
            cp_wait0();
        }
        __syncthreads();
        compute3_44(acc, cur, m0w, n0w, lane);
        __syncthreads();
    }

    const int g = lane >> 2, tg = lane & 3;
#pragma unroll
    for (int mt = 0; mt < 4; mt++)
#pragma unroll
        for (int h2 = 0; h2 < 2; h2++) {
            const size_t m = (size_t)(m0 + m0w + mt * 16 + h2 * 8 + g);
#pragma unroll
            for (int nt = 0; nt < 4; nt++) {
                const int ncol = n0 + n0w + nt * 8 + tg * 2;
                *(u32*)(C + m * 512 + ncol) =
                    pack2h(__float2half(acc[mt][nt][h2 * 2]),
                           __float2half(acc[mt][nt][h2 * 2 + 1]));
            }
        }
}

// ---------------------------------------------------------------------------
// gemm1: single-bf16 (1 MMA), K=512, cp.async double-buffered.
// EPI 0: C -> bf16 (V proj).  EPI 1: C + R -> f32 Yf (out proj).
// ---------------------------------------------------------------------------
template<int EPI>
__global__ __launch_bounds__(256)
void gemm1_k(const bf16* __restrict__ A, const bf16* __restrict__ Bw,
             bf16* __restrict__ Cb, const float* __restrict__ R,
             float* __restrict__ Yf)
{
    __shared__ __align__(16) char sm[SM_G1];
    const int tid = threadIdx.x, lane = tid & 31, wi = tid >> 5;
    const int m0 = blockIdx.y * 128, n0 = blockIdx.x * 128;
    const int m0w = (wi >> 2) * 64, n0w = (wi & 3) * 32;
    const u32 sb = cvta_smem(sm);
    const int r = tid >> 1, hf = tid & 1;
    const u32 soff = (u32)(r * 80 + hf * 32);

    float acc[4][4][4];
#pragma unroll
    for (int i = 0; i < 4; i++)
#pragma unroll
        for (int j = 0; j < 4; j++)
#pragma unroll
            for (int q = 0; q < 4; q++) acc[i][j][q] = 0.f;

    auto load_stage = [&](int c, u32 sbuf) {
        const size_t ao = (size_t)(m0 + r) * 512 + c * 32 + hf * 16;
        const size_t bo = (size_t)(n0 + r) * 512 + c * 32 + hf * 16;
        cp16(sbuf + soff,              A + ao);
        cp16(sbuf + soff + 16,         A + ao + 8);
        cp16(sbuf + TILE + soff,       Bw + bo);
        cp16(sbuf + TILE + soff + 16,  Bw + bo + 8);
    };

    load_stage(0, sb);
    cp_commit();
    for (int c = 0; c < 16; c++) {
        const u32 cur = sb + (u32)((c & 1) * G1_BUF);
        if (c + 1 < 16) {
            load_stage(c + 1, sb + (u32)(((c + 1) & 1) * G1_BUF));
            cp_commit();
            cp_wait1();
        } else {
            cp_wait0();
        }
        __syncthreads();
        compute1_44(acc, cur, m0w, n0w, lane);
        __syncthreads();
    }

    const int g = lane >> 2, tg = lane & 3;
#pragma unroll
    for (int mt = 0; mt < 4; mt++)
#pragma unroll
        for (int h2 = 0; h2 < 2; h2++) {
            const size_t m = (size_t)(m0 + m0w + mt * 16 + h2 * 8 + g);
#pragma unroll
            for (int nt = 0; nt < 4; nt++) {
                const int ncol = n0 + n0w + nt * 8 + tg * 2;
                const float x0 = acc[mt][nt][h2 * 2], x1 = acc[mt][nt][h2 * 2 + 1];
                if (EPI == 0) {
                    *(u32*)(Cb + m * 512 + ncol) =
                        pack2(__float2bfloat16(x0), __float2bfloat16(x1));
                } else {
                    const float2 rv = *(const float2*)(R + m * 512 + ncol);
                    *(float2*)(Yf + m * 512 + ncol) = make_float2(x0 + rv.x, x1 + rv.y);
                }
            }
        }
}

// ---------------------------------------------------------------------------
// Scores: fp16 x fp16 (1 MMA). exp -> attn f32 (unnormalized) + rowsums.
// ---------------------------------------------------------------------------
__global__ __launch_bounds__(256)
void scores_k(const f16* __restrict__ Qh, const f16* __restrict__ Kh,
              const unsigned char* __restrict__ mask,
              float* __restrict__ attn, float* __restrict__ rowsum)
{
    __shared__ __align__(16) char sm[SM_SC];
    const int tid = threadIdx.x, lane = tid & 31, wi = tid >> 5;
    const int bh = blockIdx.z, b_ = bh >> 3, h_ = bh & 7;
    const int q0 = blockIdx.y * 128, kt0 = blockIdx.x * 128;
    const int m0w = (wi >> 2) * 64, n0w = (wi & 3) * 32;
    const u32 sb = cvta_smem(sm);
    const int r = tid >> 1, hf = tid & 1;
    const u32 soff = (u32)(r * 80 + hf * 32);
    const int la15 = lane & 15, lc = lane >> 4;
    const int l7 = lane & 7, lb = (lane >> 3) & 1;

    float acc[4][4][4];
#pragma unroll
    for (int i = 0; i < 4; i++)
#pragma unroll
        for (int j = 0; j < 4; j++)
#pragma unroll
            for (int q = 0; q < 4; q++) acc[i][j][q] = 0.f;

#pragma unroll
    for (int c = 0; c < 2; c++) {
        const int k0 = h_ * 64 + c * 32;
        {
            const uint4* qp = (const uint4*)(Qh + (size_t)(b_ * S + q0 + r) * 512 + k0 + hf * 16);
            *(uint4*)(sm + SC_Q + soff)      = qp[0];
            *(uint4*)(sm + SC_Q + soff + 16) = qp[1];
        }
        {
            const uint4* kp = (const uint4*)(Kh + (size_t)(b_ * S + kt0 + r) * 512 + k0 + hf * 16);
            *(uint4*)(sm + SC_K + soff)      = kp[0];
            *(uint4*)(sm + SC_K + soff + 16) = kp[1];
        }
        __syncthreads();
#pragma unroll
        for (int ks = 0; ks < 2; ks++) {
            const u32 ko = (u32)(ks * 32);
            u32 a4[4][4];
#pragma unroll
            for (int mt = 0; mt < 4; mt++) {
                u32 a = sb + SC_Q + (u32)((m0w + mt * 16 + la15) * 80) + ko + lc * 16;
                ldsm4(a4[mt][0], a4[mt][1], a4[mt][2], a4[mt][3], a);
            }
            u32 b2[4][2];
#pragma unroll
            for (int nt = 0; nt < 4; nt++) {
                u32 a = sb + SC_K + (u32)((n0w + nt * 8 + l7) * 80) + ko + lb * 16;
                ldsm2(b2[nt][0], b2[nt][1], a);
            }
#pragma unroll
            for (int mt = 0; mt < 4; mt++)
#pragma unroll
                for (int nt = 0; nt < 4; nt++)
                    mma_ff(acc[mt][nt], a4[mt], b2[nt]);
        }
        __syncthreads();
    }

    const int g = lane >> 2, tg = lane & 3;
#pragma unroll
    for (int mt = 0; mt < 4; mt++)
#pragma unroll
        for (int h2 = 0; h2 < 2; h2++) {
            const int q = q0 + m0w + mt * 16 + h2 * 8 + g;
            const unsigned char* mrow = mask + (size_t)(b_ * S + q) * S + kt0;
            float* arow = attn + ((size_t)bh * S + q) * S + kt0;
            float rs = 0.f;
#pragma unroll
            for (int nt = 0; nt < 4; nt++) {
                const int col = n0w + nt * 8 + tg * 2;
                const unsigned short mv = *(const unsigned short*)(mrow + col);
                const float e0 = (mv & 0xff) ? 0.f : __expf(acc[mt][nt][h2 * 2]     * 0.125f);
                const float e1 = (mv >> 8)   ? 0.f : __expf(acc[mt][nt][h2 * 2 + 1] * 0.125f);
                *(float2*)(arow + col) = make_float2(e0, e1);
                rs += e0 + e1;
            }
            rs += __shfl_xor_sync(0xffffffffu, rs, 1);
            rs += __shfl_xor_sync(0xffffffffu, rs, 2);
            if (tg == 0) atomicAdd(&rowsum[(size_t)bh * S + q], rs);
        }
}

// ---------------------------------------------------------------------------
// PV: normalize attn in place (final output #2) and O = P @ V (1 MMA).
// cp.async double-buffered V, register-staged P. O -> bf16 (for out-proj A).
// ---------------------------------------------------------------------------
__global__ __launch_bounds__(256)
void pv_k(float* __restrict__ attn, const bf16* __restrict__ Vb,
          const float* __restrict__ rowsum, bf16* __restrict__ Ob)
{
    __shared__ __align__(16) char sm[SM_PV];
    const int tid = threadIdx.x, lane = tid & 31, wi = tid >> 5;
    const int bh = blockIdx.y, b_ = bh >> 3, h_ = bh & 7;
    const int q0 = blockIdx.x * 128;
    const int m0w = (wi >> 1) * 32, n0w = (wi & 1) * 32;
    const u32 sb = cvta_smem(sm);
    float* rinv_s = (float*)(sm + PV_RI);
    if (tid < 128) rinv_s[tid] = 1.0f / rowsum[(size_t)bh * S + q0 + tid];
    __syncthreads();

    const int r = tid >> 1, hf = tid & 1;
    const u32 soff = (u32)(r * 80 + hf * 32);
    const int vr = tid >> 3, vc = tid & 7;
    float* arow = attn + ((size_t)bh * S + q0 + r) * S + hf * 16;
    const float rv = rinv_s[r];
    const int la15 = lane & 15, lc = lane >> 4;
    const u32 pbu[2] = {sb + PV_P0, sb + PV_P1};
    const u32 vbu[2] = {sb + PV_V0, sb + PV_V1};
    char* const pbc[2] = {sm + PV_P0, sm + PV_P1};

    float acc[2][4][4];
#pragma unroll
    for (int i = 0; i < 2; i++)
#pragma unroll
        for (int j = 0; j < 4; j++)
#pragma unroll
            for (int q = 0; q < 4; q++) acc[i][j][q] = 0.f;

    float4 pr[4];
    {
        cp16(vbu[0] + (u32)(vr * 144 + vc * 16),
             Vb + (size_t)(b_ * S + vr) * 512 + h_ * 64 + vc * 8);
        cp_commit();
        float4* gp = (float4*)arow;
#pragma unroll
        for (int i = 0; i < 4; i++) pr[i] = gp[i];
#pragma unroll
        for (int i = 0; i < 4; i++) {
            pr[i].x *= rv; pr[i].y *= rv; pr[i].z *= rv; pr[i].w *= rv;
            gp[i] = pr[i];
        }
        *(uint4*)(pbc[0] + soff)      = cvt8(pr[0], pr[1]);
        *(uint4*)(pbc[0] + soff + 16) = cvt8(pr[2], pr[3]);
        cp_wait0();
        __syncthreads();
    }

    for (int c = 0; c < 64; c++) {
        const int cur = c & 1, nxt = cur ^ 1;
        const int ktn = (c + 1) * 32;
        if (c < 63) {
            cp16(vbu[nxt] + (u32)(vr * 144 + vc * 16),
                 Vb + (size_t)(b_ * S + ktn + vr) * 512 + h_ * 64 + vc * 8);
            cp_commit();
            float4* gp = (float4*)(arow + ktn);
#pragma unroll
            for (int i = 0; i < 4; i++) pr[i] = gp[i];
        }
#pragma unroll
        for (int ks = 0; ks < 2; ks++) {
            const u32 ko = (u32)(ks * 32);
            u32 a4[2][4];
#pragma unroll
            for (int mt = 0; mt < 2; mt++) {
                u32 a = pbu[cur] + (u32)((m0w + mt * 16 + la15) * 80) + ko + lc * 16;
                ldsm4(a4[mt][0], a4[mt][1], a4[mt][2], a4[mt][3], a);
            }
            u32 b2[4][2];
#pragma unroll
            for (int nt = 0; nt < 4; nt++) {
                u32 a = vbu[cur] + (u32)((ks * 16 + la15) * 144 + (n0w + nt * 8) * 2);
                ldsm2t(b2[nt][0], b2[nt][1], a);
            }
#pragma unroll
            for (int mt = 0; mt < 2; mt++)
#pragma unroll
                for (int nt = 0; nt < 4; nt++)
                    mma_bb(acc[mt][nt], a4[mt], b2[nt]);
        }
        if (c < 63) {
            float4* gp = (float4*)(arow + ktn);
#pragma unroll
            for (int i = 0; i < 4; i++) {
                pr[i].x *= rv; pr[i].y *= rv; pr[i].z *= rv; pr[i].w *= rv;
                gp[i] = pr[i];
            }
            *(uint4*)(pbc[nxt] + soff)      = cvt8(pr[0], pr[1]);
            *(uint4*)(pbc[nxt] + soff + 16) = cvt8(pr[2], pr[3]);
        }
        cp_wait0();
        __syncthreads();
    }

    const int g = lane >> 2, tg = lane & 3;
#pragma unroll
    for (int mt = 0; mt < 2; mt++)
#pragma unroll
        for (int h2 = 0; h2 < 2; h2++) {
            const size_t m = (size_t)(b_ * S + q0 + m0w + mt * 16 + h2 * 8 + g);
#pragma unroll
            for (int nt = 0; nt < 4; nt++) {
                const int ncol = h_ * 64 + n0w + nt * 8 + tg * 2;
                *(u32*)(Ob + m * 512 + ncol) =
                    pack2(__float2bfloat16(acc[mt][nt][h2 * 2]),
                          __float2bfloat16(acc[mt][nt][h2 * 2 + 1]));
            }
        }
}

// ---------------------------------------------------------------------------
// Row LayerNorm
// ---------------------------------------------------------------------------
__global__ __launch_bounds__(128)
void ln_k(const float* __restrict__ X, const float* __restrict__ gam,
          const float* __restrict__ bet, float* __restrict__ out)
{
    __shared__ float red[4];
    const int row = blockIdx.x, tid = threadIdx.x;
    const int lane = tid & 31, wid = tid >> 5;
    const float4 x = *(const float4*)(X + (size_t)row * D + tid * 4);

    float s = x.x + x.y + x.z + x.w;
#pragma unroll
    for (int off = 16; off > 0; off >>= 1) s += __shfl_xor_sync(~0u, s, off);
    if (lane == 0) red[wid] = s;
    __syncthreads();
    const float mu = (red[0] + red[1] + red[2] + red[3]) * (1.0f / D);
    __syncthreads();

    const float4 dx = make_float4(x.x - mu, x.y - mu, x.z - mu, x.w - mu);
    float q = dx.x * dx.x + dx.y * dx.y + dx.z * dx.z + dx.w * dx.w;
#pragma unroll
    for (int off = 16; off > 0; off >>= 1) q += __shfl_xor_sync(~0u, q, off);
    if (lane == 0) red[wid] = q;
    __syncthreads();
    const float var = (red[0] + red[1] + red[2] + red[3]) * (1.0f / D);
    const float inv = rsqrtf(var + 1e-5f);

    const float4 g  = *(const float4*)(gam + tid * 4);
    const float4 bb = *(const float4*)(bet + tid * 4);
    float4 y;
    y.x = dx.x * inv * g.x + bb.x;
    y.y = dx.y * inv * g.y + bb.y;
    y.z = dx.z * inv * g.z + bb.z;
    y.w = dx.w * inv * g.w + bb.w;
    *(float4*)(out + (size_t)row * D + tid * 4) = y;
}

// ---------------------------------------------------------------------------
extern "C" void kernel_launch(void* const* d_in, const int* in_sizes, int n_in,
                              void* d_out, int out_size)
{
    (void)in_sizes; (void)n_in;
    const float* Xq = (const float*)d_in[0];
    const float* Xk = (const float*)d_in[1];
    const float* Xv = (const float*)d_in[2];
    const unsigned char* mask = (const unsigned char*)d_in[3];
    const float* Wq = (const float*)d_in[4];
    const float* Wk = (const float*)d_in[5];
    const float* Wv = (const float*)d_in[6];
    const float* Wo = (const float*)d_in[7];
    const float* gam = (const float*)d_in[8];
    const float* bet = (const float*)d_in[9];
    float* out = (float*)d_out;

    bf16 *gWq, *gWk, *gWv, *gWo, *gXq, *gXk, *gXv, *gVb, *gOb;
    f16 *gQh, *gKh;
    float *gY, *grs, *gfb;
    cudaGetSymbolAddress((void**)&gWq, g_Wq);
    cudaGetSymbolAddress((void**)&gWk, g_Wk);
    cudaGetSymbolAddress((void**)&gWv, g_Wv);
    cudaGetSymbolAddress((void**)&gWo, g_Wo);
    cudaGetSymbolAddress((void**)&gXq, g_Xq);
    cudaGetSymbolAddress((void**)&gXk, g_Xk);
    cudaGetSymbolAddress((void**)&gXv, g_Xv);
    cudaGetSymbolAddress((void**)&gQh, g_Qh);
    cudaGetSymbolAddress((void**)&gKh, g_Kh);
    cudaGetSymbolAddress((void**)&gVb, g_Vb);
    cudaGetSymbolAddress((void**)&gOb, g_Ob);
    cudaGetSymbolAddress((void**)&gY, g_Y);
    cudaGetSymbolAddress((void**)&grs, g_rowsum);
    cudaGetSymbolAddress((void**)&gfb, g_attn_fb);

    static_assert(SM_G3 == 81920, "smem");
    cudaFuncSetAttribute(gemm3_k, cudaFuncAttributeMaxDynamicSharedMemorySize, SM_G3);

    float* attnp = ((long long)out_size >= OUT_ELEMS + ATTN_ELEMS)
                       ? (out + OUT_ELEMS) : gfb;

    // 1) prep: weights + inputs -> bf16 (batched)
    wsplit2_k<<<dim3(1024, 1, 2), 256>>>(Wq, Wk, gWq, gWk);
    wsingle2_k<<<dim3(1024, 1, 2), 256>>>(Wv, Wo, gWv, gWo);
    xsplit2_k<<<dim3(4096, 1, 2), 256>>>(Xq, Xk, gXq, gXk);
    xsingle_k<<<4096, 256>>>(Xv, gXv);
    cudaMemsetAsync(grs, 0, sizeof(float) * BH * S);

    // 2) projections: Q+K batched split-bf16, V single
    gemm3_k<<<dim3(4, 64, 2), 256, SM_G3>>>(gXq, gWq, gQh, gXk, gWk, gKh);
    gemm1_k<0><<<dim3(4, 64), 256>>>(gXv, gWv, gVb, nullptr, nullptr);

    // 3) scores + softmax numerators
    scores_k<<<dim3(16, 16, 32), 256>>>(gQh, gKh, mask, attnp, grs);

    // 4) normalize (finalizes attn output) + PV -> O bf16
    pv_k<<<dim3(16, 32), 256>>>(attnp, gVb, grs, gOb);

    // 5) out proj + residual, then LayerNorm
    gemm1_k<1><<<dim3(4, 64), 256>>>(gOb, gWo, nullptr, Xq, gY);
    ln_k<<<MTOK, 128>>>(gY, gam, bet, out);
}

// round 14
// speedup vs baseline: 2.4884x; 1.1696x over previous
#include <cuda_runtime.h>
#include <cuda_fp16.h>
#include <cstdint>

// ---------------------------------------------------------------------------
// MHA block, all GEMMs single fp16 mma.sync (error-budgeted):
//   proj Q/K/V : fp16 x fp16 (batched, cp.async pipelined) -> fp16
//   scores     : fp16 MMA -> exp -> UNNORMALIZED attn fp16 + rowsums
//   pv         : O = rinv * (P_unnorm @ V)  (normalization factored out);
//                writes normalized f32 attn (output #2) from smem; O fp16
//   out proj   : fp16 MMA + residual -> f32 -> LayerNorm (output #1)
// ---------------------------------------------------------------------------

using f16 = __half;
typedef unsigned int u32;

namespace {
constexpr int B = 4, S = 2048, D = 512, H = 8, BH = 32, MTOK = 8192;
constexpr long long OUT_ELEMS  = (long long)MTOK * D;
constexpr long long ATTN_ELEMS = (long long)BH * S * (long long)S;

// 128 rows x 32 fp16 (64B) + 16B pad = 80B pitch
constexpr int TILE = 10240;
constexpr int G_BUF = 2 * TILE, SM_G = 2 * G_BUF;          // 40960
// scores smem
constexpr int SC_Q = 0, SC_K = TILE, SM_SC = 2 * TILE;
// pv smem: P 128x144B x2, V 64x144B x2, rinv
constexpr int PV_P0 = 0, PV_P1 = 18432, PV_V0 = 36864, PV_V1 = 46080,
              PV_RI = 55296, SM_PV = 55808;
}

// ---- device scratch ----------------------------------------------------------
__device__ f16   g_Wt[4][(size_t)D * D];      // Wq,Wk,Wv,Wo transposed fp16
__device__ f16   g_Xh[3][(size_t)MTOK * D];   // Xq,Xk,Xv fp16
__device__ f16   g_Qh[(size_t)MTOK * D];
__device__ f16   g_Kh[(size_t)MTOK * D];
__device__ f16   g_Vh[(size_t)MTOK * D];
__device__ f16   g_Oh[(size_t)MTOK * D];
__device__ f16   g_Ph[(size_t)BH * S * (size_t)S];   // unnormalized exp, fp16
__device__ float g_Y[(size_t)MTOK * D];
__device__ float g_rowsum[BH * S];
__device__ float g_attn_fb[(size_t)BH * S * (size_t)S];

// ---- PTX helpers ---------------------------------------------------------------
__device__ __forceinline__ u32 cvta_smem(const void* p) {
    u32 a;
    asm("{ .reg .u64 t; cvta.to.shared.u64 t, %1; cvt.u32.u64 %0, t; }"
        : "=r"(a) : "l"(p));
    return a;
}
__device__ __forceinline__ void ldsm4(u32& r0, u32& r1, u32& r2, u32& r3, u32 a) {
    asm volatile("ldmatrix.sync.aligned.m8n8.x4.shared.b16 {%0,%1,%2,%3}, [%4];"
                 : "=r"(r0), "=r"(r1), "=r"(r2), "=r"(r3) : "r"(a));
}
__device__ __forceinline__ void ldsm2(u32& r0, u32& r1, u32 a) {
    asm volatile("ldmatrix.sync.aligned.m8n8.x2.shared.b16 {%0,%1}, [%2];"
                 : "=r"(r0), "=r"(r1) : "r"(a));
}
__device__ __forceinline__ void ldsm2t(u32& r0, u32& r1, u32 a) {
    asm volatile("ldmatrix.sync.aligned.m8n8.x2.trans.shared.b16 {%0,%1}, [%2];"
                 : "=r"(r0), "=r"(r1) : "r"(a));
}
__device__ __forceinline__ void mma_ff(float* c, const u32* a, const u32* b) {
    asm volatile(
        "mma.sync.aligned.m16n8k16.row.col.f32.f16.f16.f32 "
        "{%0,%1,%2,%3}, {%4,%5,%6,%7}, {%8,%9}, {%0,%1,%2,%3};"
        : "+f"(c[0]), "+f"(c[1]), "+f"(c[2]), "+f"(c[3])
        : "r"(a[0]), "r"(a[1]), "r"(a[2]), "r"(a[3]), "r"(b[0]), "r"(b[1]));
}
__device__ __forceinline__ void cp16(u32 dst, const void* src) {
    asm volatile("cp.async.cg.shared.global [%0], [%1], 16;" :: "r"(dst), "l"(src));
}
__device__ __forceinline__ void cp_commit() {
    asm volatile("cp.async.commit_group;" ::: "memory");
}
__device__ __forceinline__ void cp_wait0() {
    asm volatile("cp.async.wait_group 0;" ::: "memory");
}
__device__ __forceinline__ void cp_wait1() {
    asm volatile("cp.async.wait_group 1;" ::: "memory");
}
__device__ __forceinline__ u32 pack2h(f16 a, f16 b) {
    return (u32)__half_as_ushort(a) | ((u32)__half_as_ushort(b) << 16);
}

// ---------------------------------------------------------------------------
// Prep: weights -> W^T fp16 (z=4); inputs -> fp16 (z=3)
// ---------------------------------------------------------------------------
__global__ void whalf_k(const float* __restrict__ w0, const float* __restrict__ w1,
                        const float* __restrict__ w2, const float* __restrict__ w3,
                        f16* __restrict__ o) {
    const float* w = (blockIdx.z == 0) ? w0 : (blockIdx.z == 1) ? w1
                   : (blockIdx.z == 2) ? w2 : w3;
    f16* t = o + (size_t)blockIdx.z * D * D;
    int i = blockIdx.x * 256 + threadIdx.x;
    int k = i >> 9, n = i & 511;
    t[(size_t)n * 512 + k] = __float2half(w[i]);
}
__global__ void xhalf_k(const float* __restrict__ x0, const float* __restrict__ x1,
                        const float* __restrict__ x2, f16* __restrict__ o) {
    const float* x = (blockIdx.z == 0) ? x0 : (blockIdx.z == 1) ? x1 : x2;
    f16* t = o + (size_t)blockIdx.z * MTOK * D;
    const size_t i = ((size_t)blockIdx.x * 256 + threadIdx.x) * 4;
    float4 v = *(const float4*)(x + i);
    *(uint2*)(t + i) = make_uint2(pack2h(__float2half(v.x), __float2half(v.y)),
                                  pack2h(__float2half(v.z), __float2half(v.w)));
}

// ---------------------------------------------------------------------------
// One BK=32 fp16 stage, warp tile 64x32 (MT=4, NT=4)
// ---------------------------------------------------------------------------
__device__ __forceinline__ void compute_ff44(float acc[4][4][4], u32 sbuf,
                                             int m0w, int n0w, int lane)
{
    const int la15 = lane & 15, lc = lane >> 4;
    const int l7 = lane & 7, lb = (lane >> 3) & 1;
#pragma unroll
    for (int ks = 0; ks < 2; ks++) {
        const u32 ko = (u32)(ks * 32);
        u32 a4[4][4];
#pragma unroll
        for (int mt = 0; mt < 4; mt++) {
            u32 a = sbuf + (u32)((m0w + mt * 16 + la15) * 80) + ko + lc * 16;
            ldsm4(a4[mt][0], a4[mt][1], a4[mt][2], a4[mt][3], a);
        }
        u32 b2[4][2];
#pragma unroll
        for (int nt = 0; nt < 4; nt++) {
            u32 a = sbuf + TILE + (u32)((n0w + nt * 8 + l7) * 80) + ko + lb * 16;
            ldsm2(b2[nt][0], b2[nt][1], a);
        }
#pragma unroll
        for (int mt = 0; mt < 4; mt++)
#pragma unroll
            for (int nt = 0; nt < 4; nt++)
                mma_ff(acc[mt][nt], a4[mt], b2[nt]);
    }
}

// ---------------------------------------------------------------------------
// gemmf3: batched Q/K/V projections, fp16, cp.async double-buffered -> fp16 C
// ---------------------------------------------------------------------------
__global__ __launch_bounds__(256)
void gemmf3_k(const f16* __restrict__ Xh, const f16* __restrict__ Wt,
              f16* __restrict__ C0, f16* __restrict__ C1, f16* __restrict__ C2)
{
    __shared__ __align__(16) char sm[SM_G];
    const f16* A = Xh + (size_t)blockIdx.z * MTOK * D;
    const f16* Bw = Wt + (size_t)blockIdx.z * D * D;
    f16* C = (blockIdx.z == 0) ? C0 : (blockIdx.z == 1) ? C1 : C2;

    const int tid = threadIdx.x, lane = tid & 31, wi = tid >> 5;
    const int m0 = blockIdx.y * 128, n0 = blockIdx.x * 128;
    const int m0w = (wi >> 2) * 64, n0w = (wi & 3) * 32;
    const u32 sb = cvta_smem(sm);
    const int r = tid >> 1, hf = tid & 1;
    const u32 soff = (u32)(r * 80 + hf * 32);

    float acc[4][4][4];
#pragma unroll
    for (int i = 0; i < 4; i++)
#pragma unroll
        for (int j = 0; j < 4; j++)
#pragma unroll
            for (int q = 0; q < 4; q++) acc[i][j][q] = 0.f;

    auto load_stage = [&](int c, u32 sbuf) {
        const size_t ao = (size_t)(m0 + r) * 512 + c * 32 + hf * 16;
        const size_t bo = (size_t)(n0 + r) * 512 + c * 32 + hf * 16;
        cp16(sbuf + soff,             A + ao);
        cp16(sbuf + soff + 16,        A + ao + 8);
        cp16(sbuf + TILE + soff,      Bw + bo);
        cp16(sbuf + TILE + soff + 16, Bw + bo + 8);
    };

    load_stage(0, sb);
    cp_commit();
    for (int c = 0; c < 16; c++) {
        const u32 cur = sb + (u32)((c & 1) * G_BUF);
        if (c + 1 < 16) {
            load_stage(c + 1, sb + (u32)(((c + 1) & 1) * G_BUF));
            cp_commit();
            cp_wait1();
        } else {
            cp_wait0();
        }
        __syncthreads();
        compute_ff44(acc, cur, m0w, n0w, lane);
        __syncthreads();
    }

    const int g = lane >> 2, tg = lane & 3;
#pragma unroll
    for (int mt = 0; mt < 4; mt++)
#pragma unroll
        for (int h2 = 0; h2 < 2; h2++) {
            const size_t m = (size_t)(m0 + m0w + mt * 16 + h2 * 8 + g);
#pragma unroll
            for (int nt = 0; nt < 4; nt++) {
                const int ncol = n0 + n0w + nt * 8 + tg * 2;
                *(u32*)(C + m * 512 + ncol) =
                    pack2h(__float2half(acc[mt][nt][h2 * 2]),
                           __float2half(acc[mt][nt][h2 * 2 + 1]));
            }
        }
}

// ---------------------------------------------------------------------------
// gemmo: out proj fp16 MMA + residual -> f32 Y
// ---------------------------------------------------------------------------
__global__ __launch_bounds__(256)
void gemmo_k(const f16* __restrict__ A, const f16* __restrict__ Bw,
             const float* __restrict__ R, float* __restrict__ Yf)
{
    __shared__ __align__(16) char sm[SM_G];
    const int tid = threadIdx.x, lane = tid & 31, wi = tid >> 5;
    const int m0 = blockIdx.y * 128, n0 = blockIdx.x * 128;
    const int m0w = (wi >> 2) * 64, n0w = (wi & 3) * 32;
    const u32 sb = cvta_smem(sm);
    const int r = tid >> 1, hf = tid & 1;
    const u32 soff = (u32)(r * 80 + hf * 32);

    float acc[4][4][4];
#pragma unroll
    for (int i = 0; i < 4; i++)
#pragma unroll
        for (int j = 0; j < 4; j++)
#pragma unroll
            for (int q = 0; q < 4; q++) acc[i][j][q] = 0.f;

    auto load_stage = [&](int c, u32 sbuf) {
        const size_t ao = (size_t)(m0 + r) * 512 + c * 32 + hf * 16;
        const size_t bo = (size_t)(n0 + r) * 512 + c * 32 + hf * 16;
        cp16(sbuf + soff,             A + ao);
        cp16(sbuf + soff + 16,        A + ao + 8);
        cp16(sbuf + TILE + soff,      Bw + bo);
        cp16(sbuf + TILE + soff + 16, Bw + bo + 8);
    };

    load_stage(0, sb);
    cp_commit();
    for (int c = 0; c < 16; c++) {
        const u32 cur = sb + (u32)((c & 1) * G_BUF);
        if (c + 1 < 16) {
            load_stage(c + 1, sb + (u32)(((c + 1) & 1) * G_BUF));
            cp_commit();
            cp_wait1();
        } else {
            cp_wait0();
        }
        __syncthreads();
        compute_ff44(acc, cur, m0w, n0w, lane);
        __syncthreads();
    }

    const int g = lane >> 2, tg = lane & 3;
#pragma unroll
    for (int mt = 0; mt < 4; mt++)
#pragma unroll
        for (int h2 = 0; h2 < 2; h2++) {
            const size_t m = (size_t)(m0 + m0w + mt * 16 + h2 * 8 + g);
#pragma unroll
            for (int nt = 0; nt < 4; nt++) {
                const int ncol = n0 + n0w + nt * 8 + tg * 2;
                const float2 rv = *(const float2*)(R + m * 512 + ncol);
                *(float2*)(Yf + m * 512 + ncol) =
                    make_float2(acc[mt][nt][h2 * 2] + rv.x,
                                acc[mt][nt][h2 * 2 + 1] + rv.y);
            }
        }
}

// ---------------------------------------------------------------------------
// Scores: fp16 MMA -> exp -> UNNORMALIZED attn fp16 (g_Ph) + rowsums
// ---------------------------------------------------------------------------
__global__ __launch_bounds__(256)
void scores_k(const f16* __restrict__ Qh, const f16* __restrict__ Kh,
              const unsigned char* __restrict__ mask,
              f16* __restrict__ Ph, float* __restrict__ rowsum)
{
    __shared__ __align__(16) char sm[SM_SC];
    const int tid = threadIdx.x, lane = tid & 31, wi = tid >> 5;
    const int bh = blockIdx.z, b_ = bh >> 3, h_ = bh & 7;
    const int q0 = blockIdx.y * 128, kt0 = blockIdx.x * 128;
    const int m0w = (wi >> 2) * 64, n0w = (wi & 3) * 32;
    const u32 sb = cvta_smem(sm);
    const int r = tid >> 1, hf = tid & 1;
    const u32 soff = (u32)(r * 80 + hf * 32);
    const int la15 = lane & 15, lc = lane >> 4;
    const int l7 = lane & 7, lb = (lane >> 3) & 1;

    float acc[4][4][4];
#pragma unroll
    for (int i = 0; i < 4; i++)
#pragma unroll
        for (int j = 0; j < 4; j++)
#pragma unroll
            for (int q = 0; q < 4; q++) acc[i][j][q] = 0.f;

#pragma unroll
    for (int c = 0; c < 2; c++) {
        const int k0 = h_ * 64 + c * 32;
        {
            const uint4* qp = (const uint4*)(Qh + (size_t)(b_ * S + q0 + r) * 512 + k0 + hf * 16);
            *(uint4*)(sm + SC_Q + soff)      = qp[0];
            *(uint4*)(sm + SC_Q + soff + 16) = qp[1];
        }
        {
            const uint4* kp = (const uint4*)(Kh + (size_t)(b_ * S + kt0 + r) * 512 + k0 + hf * 16);
            *(uint4*)(sm + SC_K + soff)      = kp[0];
            *(uint4*)(sm + SC_K + soff + 16) = kp[1];
        }
        __syncthreads();
#pragma unroll
        for (int ks = 0; ks < 2; ks++) {
            const u32 ko = (u32)(ks * 32);
            u32 a4[4][4];
#pragma unroll
            for (int mt = 0; mt < 4; mt++) {
                u32 a = sb + SC_Q + (u32)((m0w + mt * 16 + la15) * 80) + ko + lc * 16;
                ldsm4(a4[mt][0], a4[mt][1], a4[mt][2], a4[mt][3], a);
            }
            u32 b2[4][2];
#pragma unroll
            for (int nt = 0; nt < 4; nt++) {
                u32 a = sb + SC_K + (u32)((n0w + nt * 8 + l7) * 80) + ko + lb * 16;
                ldsm2(b2[nt][0], b2[nt][1], a);
            }
#pragma unroll
            for (int mt = 0; mt < 4; mt++)
#pragma unroll
                for (int nt = 0; nt < 4; nt++)
                    mma_ff(acc[mt][nt], a4[mt], b2[nt]);
        }
        __syncthreads();
    }

    const int g = lane >> 2, tg = lane & 3;
#pragma unroll
    for (int mt = 0; mt < 4; mt++)
#pragma unroll
        for (int h2 = 0; h2 < 2; h2++) {
            const int q = q0 + m0w + mt * 16 + h2 * 8 + g;
            const unsigned char* mrow = mask + (size_t)(b_ * S + q) * S + kt0;
            f16* prow = Ph + ((size_t)bh * S + q) * S + kt0;
            float rs = 0.f;
#pragma unroll
            for (int nt = 0; nt < 4; nt++) {
                const int col = n0w + nt * 8 + tg * 2;
                const unsigned short mv = *(const unsigned short*)(mrow + col);
                const float e0 = (mv & 0xff) ? 0.f : __expf(acc[mt][nt][h2 * 2]     * 0.125f);
                const float e1 = (mv >> 8)   ? 0.f : __expf(acc[mt][nt][h2 * 2 + 1] * 0.125f);
                *(u32*)(prow + col) = pack2h(__float2half(e0), __float2half(e1));
                rs += e0 + e1;
            }
            rs += __shfl_xor_sync(0xffffffffu, rs, 1);
            rs += __shfl_xor_sync(0xffffffffu, rs, 2);
            if (tg == 0) atomicAdd(&rowsum[(size_t)bh * S + q], rs);
        }
}

// ---------------------------------------------------------------------------
// PV: O = rinv * (P_unnorm @ V); writes normalized f32 attn from smem.
// cp.async double-buffered P (raw fp16) and V. 8 warps = 4m x 2n (32x32).
// ---------------------------------------------------------------------------
__global__ __launch_bounds__(256)
void pv_k(const f16* __restrict__ Ph, const f16* __restrict__ Vh,
          const float* __restrict__ rowsum, float* __restrict__ attn,
          f16* __restrict__ Oh)
{
    extern __shared__ __align__(16) char sm[];
    const int tid = threadIdx.x, lane = tid & 31, wi = tid >> 5;
    const int bh = blockIdx.y, b_ = bh >> 3, h_ = bh & 7;
    const int q0 = blockIdx.x * 128;
    const int m0w = (wi >> 1) * 32, n0w = (wi & 1) * 32;
    const u32 sb = cvta_smem(sm);
    float* rinv_s = (float*)(sm + PV_RI);
    if (tid < 128) rinv_s[tid] = 1.0f / rowsum[(size_t)bh * S + q0 + tid];
    __syncthreads();

    const int r = tid >> 1, hf = tid & 1;
    const float rv = rinv_s[r];
    const int vr = tid >> 3, vs = tid & 7;
    const int la15 = lane & 15, lc = lane >> 4;
    const u32 pbu[2] = {sb + PV_P0, sb + PV_P1};
    const u32 vbu[2] = {sb + PV_V0, sb + PV_V1};
    char* const pbc[2] = {sm + PV_P0, sm + PV_P1};

    const f16* Prow = Ph + ((size_t)bh * S + q0 + r) * S;
    float* Arow = attn + ((size_t)bh * S + q0 + r) * S;

    float acc[2][4][4];
#pragma unroll
    for (int i = 0; i < 2; i++)
#pragma unroll
        for (int j = 0; j < 4; j++)
#pragma unroll
            for (int q = 0; q < 4; q++) acc[i][j][q] = 0.f;

    auto load_stage = [&](int c, int buf) {
        const int kt = c * 64;
        // P: 128 q x 64 k fp16
#pragma unroll
        for (int j = 0; j < 4; j++)
            cp16(pbu[buf] + (u32)(r * 144 + hf * 64 + j * 16),
                 Prow + kt + hf * 32 + j * 8);
        // V: 64 k x 64 dv fp16
#pragma unroll
        for (int j = 0; j < 2; j++) {
            const int row = vr + j * 32;
            cp16(vbu[buf] + (u32)(row * 144 + vs * 16),
                 Vh + (size_t)(b_ * S + kt + row) * 512 + h_ * 64 + vs * 8);
        }
    };

    load_stage(0, 0);
    cp_commit();
    for (int c = 0; c < 32; c++) {
        const int cur = c & 1;
        if (c + 1 < 32) {
            load_stage(c + 1, cur ^ 1);
            cp_commit();
            cp_wait1();
        } else {
            cp_wait0();
        }
        __syncthreads();
        // MMA on current buffers
#pragma unroll
        for (int ks = 0; ks < 4; ks++) {
            u32 a4[2][4];
#pragma unroll
            for (int mt = 0; mt < 2; mt++) {
                u32 a = pbu[cur] + (u32)((m0w + mt * 16 + la15) * 144 + ks * 32 + lc * 16);
                ldsm4(a4[mt][0], a4[mt][1], a4[mt][2], a4[mt][3], a);
            }
            u32 b2[4][2];
#pragma unroll
            for (int nt = 0; nt < 4; nt++) {
                u32 a = vbu[cur] + (u32)((ks * 16 + la15) * 144 + (n0w + nt * 8) * 2);
                ldsm2t(b2[nt][0], b2[nt][1], a);
            }
#pragma unroll
            for (int mt = 0; mt < 2; mt++)
#pragma unroll
                for (int nt = 0; nt < 4; nt++)
                    mma_ff(acc[mt][nt], a4[mt], b2[nt]);
        }
        // normalized attn write (from smem, x rinv)
        {
            const int kt = c * 64;
#pragma unroll
            for (int j = 0; j < 4; j++) {
                const uint4 pv4 = *(const uint4*)(pbc[cur] + r * 144 + hf * 64 + j * 16);
                const u32 w[4] = {pv4.x, pv4.y, pv4.z, pv4.w};
                float4 o0, o1;
                float* op = &o0.x;
#pragma unroll
                for (int e = 0; e < 4; e++) {
                    op[2 * e - (e >> 1) * 8 + (e >> 1) * 0] = 0.f;  // placeholder (overwritten)
                }
                // unpack 8 fp16 -> 8 f32 * rv
                f16 h0 = __ushort_as_half((unsigned short)(w[0] & 0xffff));
                f16 h1 = __ushort_as_half((unsigned short)(w[0] >> 16));
                f16 h2 = __ushort_as_half((unsigned short)(w[1] & 0xffff));
                f16 h3 = __ushort_as_half((unsigned short)(w[1] >> 16));
                f16 h4 = __ushort_as_half((unsigned short)(w[2] & 0xffff));
                f16 h5 = __ushort_as_half((unsigned short)(w[2] >> 16));
                f16 h6 = __ushort_as_half((unsigned short)(w[3] & 0xffff));
                f16 h7 = __ushort_as_half((unsigned short)(w[3] >> 16));
                o0 = make_float4(__half2float(h0) * rv, __half2float(h1) * rv,
                                 __half2float(h2) * rv, __half2float(h3) * rv);
                o1 = make_float4(__half2float(h4) * rv, __half2float(h5) * rv,
                                 __half2float(h6) * rv, __half2float(h7) * rv);
                float* dst = Arow + kt + hf * 32 + j * 8;
                *(float4*)dst       = o0;
                *(float4*)(dst + 4) = o1;
            }
        }
        __syncthreads();
    }

    const int g = lane >> 2, tg = lane & 3;
#pragma unroll
    for (int mt = 0; mt < 2; mt++)
#pragma unroll
        for (int h2 = 0; h2 < 2; h2++) {
            const int row = m0w + mt * 16 + h2 * 8 + g;
            const float rr = rinv_s[row];
            const size_t m = (size_t)(b_ * S + q0 + row);
#pragma unroll
            for (int nt = 0; nt < 4; nt++) {
                const int ncol = h_ * 64 + n0w + nt * 8 + tg * 2;
                *(u32*)(Oh + m * 512 + ncol) =
                    pack2h(__float2half(acc[mt][nt][h2 * 2] * rr),
                           __float2half(acc[mt][nt][h2 * 2 + 1] * rr));
            }
        }
}

// ---------------------------------------------------------------------------
// Row LayerNorm
// ---------------------------------------------------------------------------
__global__ __launch_bounds__(128)
void ln_k(const float* __restrict__ X, const float* __restrict__ gam,
          const float* __restrict__ bet, float* __restrict__ out)
{
    __shared__ float red[4];
    const int row = blockIdx.x, tid = threadIdx.x;
    const int lane = tid & 31, wid = tid >> 5;
    const float4 x = *(const float4*)(X + (size_t)row * D + tid * 4);

    float s = x.x + x.y + x.z + x.w;
#pragma unroll
    for (int off = 16; off > 0; off >>= 1) s += __shfl_xor_sync(~0u, s, off);
    if (lane == 0) red[wid] = s;
    __syncthreads();
    const float mu = (red[0] + red[1] + red[2] + red[3]) * (1.0f / D);
    __syncthreads();

    const float4 dx = make_float4(x.x - mu, x.y - mu, x.z - mu, x.w - mu);
    float q = dx.x * dx.x + dx.y * dx.y + dx.z * dx.z + dx.w * dx.w;
#pragma unroll
    for (int off = 16; off > 0; off >>= 1) q += __shfl_xor_sync(~0u, q, off);
    if (lane == 0) red[wid] = q;
    __syncthreads();
    const float var = (red[0] + red[1] + red[2] + red[3]) * (1.0f / D);
    const float inv = rsqrtf(var + 1e-5f);

    const float4 g  = *(const float4*)(gam + tid * 4);
    const float4 bb = *(const float4*)(bet + tid * 4);
    float4 y;
    y.x = dx.x * inv * g.x + bb.x;
    y.y = dx.y * inv * g.y + bb.y;
    y.z = dx.z * inv * g.z + bb.z;
    y.w = dx.w * inv * g.w + bb.w;
    *(float4*)(out + (size_t)row * D + tid * 4) = y;
}

// ---------------------------------------------------------------------------
extern "C" void kernel_launch(void* const* d_in, const int* in_sizes, int n_in,
                              void* d_out, int out_size)
{
    (void)in_sizes; (void)n_in;
    const float* Xq = (const float*)d_in[0];
    const float* Xk = (const float*)d_in[1];
    const float* Xv = (const float*)d_in[2];
    const unsigned char* mask = (const unsigned char*)d_in[3];
    const float* Wq = (const float*)d_in[4];
    const float* Wk = (const float*)d_in[5];
    const float* Wv = (const float*)d_in[6];
    const float* Wo = (const float*)d_in[7];
    const float* gam = (const float*)d_in[8];
    const float* bet = (const float*)d_in[9];
    float* out = (float*)d_out;

    f16 *gWt, *gXh, *gQh, *gKh, *gVh, *gOh, *gPh;
    float *gY, *grs, *gfb;
    cudaGetSymbolAddress((void**)&gWt, g_Wt);
    cudaGetSymbolAddress((void**)&gXh, g_Xh);
    cudaGetSymbolAddress((void**)&gQh, g_Qh);
    cudaGetSymbolAddress((void**)&gKh, g_Kh);
    cudaGetSymbolAddress((void**)&gVh, g_Vh);
    cudaGetSymbolAddress((void**)&gOh, g_Oh);
    cudaGetSymbolAddress((void**)&gPh, g_Ph);
    cudaGetSymbolAddress((void**)&gY, g_Y);
    cudaGetSymbolAddress((void**)&grs, g_rowsum);
    cudaGetSymbolAddress((void**)&gfb, g_attn_fb);
    const size_t DD = (size_t)D * D;

    cudaFuncSetAttribute(pv_k, cudaFuncAttributeMaxDynamicSharedMemorySize, SM_PV);

    float* attnp = ((long long)out_size >= OUT_ELEMS + ATTN_ELEMS)
                       ? (out + OUT_ELEMS) : gfb;

    // 1) prep: W^T fp16 (z=4), X fp16 (z=3)
    whalf_k<<<dim3(1024, 1, 4), 256>>>(Wq, Wk, Wv, Wo, gWt);
    xhalf_k<<<dim3(4096, 1, 3), 256>>>(Xq, Xk, Xv, gXh);
    cudaMemsetAsync(grs, 0, sizeof(float) * BH * S);

    // 2) projections (Q,K,V batched)
    gemmf3_k<<<dim3(4, 64, 3), 256>>>(gXh, gWt, gQh, gKh, gVh);

    // 3) scores -> unnormalized fp16 P + rowsums
    scores_k<<<dim3(16, 16, 32), 256>>>(gQh, gKh, mask, gPh, grs);

    // 4) PV (normalization factored out) + normalized attn write
    pv_k<<<dim3(16, 32), 256, SM_PV>>>(gPh, gVh, grs, attnp, gOh);

    // 5) out proj + residual, then LayerNorm
    gemmo_k<<<dim3(4, 64), 256>>>(gOh, gWt + 3 * DD, Xq, gY);
    ln_k<<<MTOK, 128>>>(gY, gam, bet, out);
}

// round 15
// speedup vs baseline: 2.9260x; 1.1759x over previous
#include <cuda_runtime.h>
#include <cuda_fp16.h>
#include <cstdint>

// ---------------------------------------------------------------------------
// MHA block, all fp16 mma.sync (error-budgeted, R14 scheme) +
// R15: L1-wavefront fixes — smem-staged mask loads & coalesced P/attn writes.
// ---------------------------------------------------------------------------

using f16 = __half;
typedef unsigned int u32;

namespace {
constexpr int B = 4, S = 2048, D = 512, H = 8, BH = 32, MTOK = 8192;
constexpr long long OUT_ELEMS  = (long long)MTOK * D;
constexpr long long ATTN_ELEMS = (long long)BH * S * (long long)S;

constexpr int TILE = 10240;                       // 128 x 80B
constexpr int G_BUF = 2 * TILE, SM_G = 2 * G_BUF;
// scores smem: Q,K tiles; mask tile; P staging overlays (after MMA)
constexpr int SC_Q = 0, SC_K = TILE, SC_MK = 20480, SC_PST = 0,
              SM_SC = 36864;                      // P stage: 128 x 272B = 34816
// pv smem: P 128x144B x2, V 64x144B x2, rinv
constexpr int PV_P0 = 0, PV_P1 = 18432, PV_V0 = 36864, PV_V1 = 46080,
              PV_RI = 55296, SM_PV = 55808;
}

// ---- device scratch ----------------------------------------------------------
__device__ f16   g_Wt[4][(size_t)D * D];
__device__ f16   g_Xh[3][(size_t)MTOK * D];
__device__ f16   g_Qh[(size_t)MTOK * D];
__device__ f16   g_Kh[(size_t)MTOK * D];
__device__ f16   g_Vh[(size_t)MTOK * D];
__device__ f16   g_Oh[(size_t)MTOK * D];
__device__ f16   g_Ph[(size_t)BH * S * (size_t)S];
__device__ float g_Y[(size_t)MTOK * D];
__device__ float g_rowsum[BH * S];
__device__ float g_attn_fb[(size_t)BH * S * (size_t)S];

// ---- PTX helpers ---------------------------------------------------------------
__device__ __forceinline__ u32 cvta_smem(const void* p) {
    u32 a;
    asm("{ .reg .u64 t; cvta.to.shared.u64 t, %1; cvt.u32.u64 %0, t; }"
        : "=r"(a) : "l"(p));
    return a;
}
__device__ __forceinline__ void ldsm4(u32& r0, u32& r1, u32& r2, u32& r3, u32 a) {
    asm volatile("ldmatrix.sync.aligned.m8n8.x4.shared.b16 {%0,%1,%2,%3}, [%4];"
                 : "=r"(r0), "=r"(r1), "=r"(r2), "=r"(r3) : "r"(a));
}
__device__ __forceinline__ void ldsm2(u32& r0, u32& r1, u32 a) {
    asm volatile("ldmatrix.sync.aligned.m8n8.x2.shared.b16 {%0,%1}, [%2];"
                 : "=r"(r0), "=r"(r1) : "r"(a));
}
__device__ __forceinline__ void ldsm2t(u32& r0, u32& r1, u32 a) {
    asm volatile("ldmatrix.sync.aligned.m8n8.x2.trans.shared.b16 {%0,%1}, [%2];"
                 : "=r"(r0), "=r"(r1) : "r"(a));
}
__device__ __forceinline__ void mma_ff(float* c, const u32* a, const u32* b) {
    asm volatile(
        "mma.sync.aligned.m16n8k16.row.col.f32.f16.f16.f32 "
        "{%0,%1,%2,%3}, {%4,%5,%6,%7}, {%8,%9}, {%0,%1,%2,%3};"
        : "+f"(c[0]), "+f"(c[1]), "+f"(c[2]), "+f"(c[3])
        : "r"(a[0]), "r"(a[1]), "r"(a[2]), "r"(a[3]), "r"(b[0]), "r"(b[1]));
}
__device__ __forceinline__ void cp16(u32 dst, const void* src) {
    asm volatile("cp.async.cg.shared.global [%0], [%1], 16;" :: "r"(dst), "l"(src));
}
__device__ __forceinline__ void cp_commit() {
    asm volatile("cp.async.commit_group;" ::: "memory");
}
__device__ __forceinline__ void cp_wait0() {
    asm volatile("cp.async.wait_group 0;" ::: "memory");
}
__device__ __forceinline__ void cp_wait1() {
    asm volatile("cp.async.wait_group 1;" ::: "memory");
}
__device__ __forceinline__ u32 pack2h(f16 a, f16 b) {
    return (u32)__half_as_ushort(a) | ((u32)__half_as_ushort(b) << 16);
}

// ---------------------------------------------------------------------------
// Prep
// ---------------------------------------------------------------------------
__global__ void whalf_k(const float* __restrict__ w0, const float* __restrict__ w1,
                        const float* __restrict__ w2, const float* __restrict__ w3,
                        f16* __restrict__ o) {
    const float* w = (blockIdx.z == 0) ? w0 : (blockIdx.z == 1) ? w1
                   : (blockIdx.z == 2) ? w2 : w3;
    f16* t = o + (size_t)blockIdx.z * D * D;
    int i = blockIdx.x * 256 + threadIdx.x;
    int k = i >> 9, n = i & 511;
    t[(size_t)n * 512 + k] = __float2half(w[i]);
}
__global__ void xhalf_k(const float* __restrict__ x0, const float* __restrict__ x1,
                        const float* __restrict__ x2, f16* __restrict__ o) {
    const float* x = (blockIdx.z == 0) ? x0 : (blockIdx.z == 1) ? x1 : x2;
    f16* t = o + (size_t)blockIdx.z * MTOK * D;
    const size_t i = ((size_t)blockIdx.x * 256 + threadIdx.x) * 4;
    float4 v = *(const float4*)(x + i);
    *(uint2*)(t + i) = make_uint2(pack2h(__float2half(v.x), __float2half(v.y)),
                                  pack2h(__float2half(v.z), __float2half(v.w)));
}

// ---------------------------------------------------------------------------
// One BK=32 fp16 stage, warp tile 64x32
// ---------------------------------------------------------------------------
__device__ __forceinline__ void compute_ff44(float acc[4][4][4], u32 sbuf,
                                             int m0w, int n0w, int lane)
{
    const int la15 = lane & 15, lc = lane >> 4;
    const int l7 = lane & 7, lb = (lane >> 3) & 1;
#pragma unroll
    for (int ks = 0; ks < 2; ks++) {
        const u32 ko = (u32)(ks * 32);
        u32 a4[4][4];
#pragma unroll
        for (int mt = 0; mt < 4; mt++) {
            u32 a = sbuf + (u32)((m0w + mt * 16 + la15) * 80) + ko + lc * 16;
            ldsm4(a4[mt][0], a4[mt][1], a4[mt][2], a4[mt][3], a);
        }
        u32 b2[4][2];
#pragma unroll
        for (int nt = 0; nt < 4; nt++) {
            u32 a = sbuf + TILE + (u32)((n0w + nt * 8 + l7) * 80) + ko + lb * 16;
            ldsm2(b2[nt][0], b2[nt][1], a);
        }
#pragma unroll
        for (int mt = 0; mt < 4; mt++)
#pragma unroll
            for (int nt = 0; nt < 4; nt++)
                mma_ff(acc[mt][nt], a4[mt], b2[nt]);
    }
}

// ---------------------------------------------------------------------------
// gemmf3: batched Q/K/V projections
// ---------------------------------------------------------------------------
__global__ __launch_bounds__(256)
void gemmf3_k(const f16* __restrict__ Xh, const f16* __restrict__ Wt,
              f16* __restrict__ C0, f16* __restrict__ C1, f16* __restrict__ C2)
{
    __shared__ __align__(16) char sm[SM_G];
    const f16* A = Xh + (size_t)blockIdx.z * MTOK * D;
    const f16* Bw = Wt + (size_t)blockIdx.z * D * D;
    f16* C = (blockIdx.z == 0) ? C0 : (blockIdx.z == 1) ? C1 : C2;

    const int tid = threadIdx.x, lane = tid & 31, wi = tid >> 5;
    const int m0 = blockIdx.y * 128, n0 = blockIdx.x * 128;
    const int m0w = (wi >> 2) * 64, n0w = (wi & 3) * 32;
    const u32 sb = cvta_smem(sm);
    const int r = tid >> 1, hf = tid & 1;
    const u32 soff = (u32)(r * 80 + hf * 32);

    float acc[4][4][4];
#pragma unroll
    for (int i = 0; i < 4; i++)
#pragma unroll
        for (int j = 0; j < 4; j++)
#pragma unroll
            for (int q = 0; q < 4; q++) acc[i][j][q] = 0.f;

    auto load_stage = [&](int c, u32 sbuf) {
        const size_t ao = (size_t)(m0 + r) * 512 + c * 32 + hf * 16;
        const size_t bo = (size_t)(n0 + r) * 512 + c * 32 + hf * 16;
        cp16(sbuf + soff,             A + ao);
        cp16(sbuf + soff + 16,        A + ao + 8);
        cp16(sbuf + TILE + soff,      Bw + bo);
        cp16(sbuf + TILE + soff + 16, Bw + bo + 8);
    };

    load_stage(0, sb);
    cp_commit();
    for (int c = 0; c < 16; c++) {
        const u32 cur = sb + (u32)((c & 1) * G_BUF);
        if (c + 1 < 16) {
            load_stage(c + 1, sb + (u32)(((c + 1) & 1) * G_BUF));
            cp_commit();
            cp_wait1();
        } else {
            cp_wait0();
        }
        __syncthreads();
        compute_ff44(acc, cur, m0w, n0w, lane);
        __syncthreads();
    }

    const int g = lane >> 2, tg = lane & 3;
#pragma unroll
    for (int mt = 0; mt < 4; mt++)
#pragma unroll
        for (int h2 = 0; h2 < 2; h2++) {
            const size_t m = (size_t)(m0 + m0w + mt * 16 + h2 * 8 + g);
#pragma unroll
            for (int nt = 0; nt < 4; nt++) {
                const int ncol = n0 + n0w + nt * 8 + tg * 2;
                *(u32*)(C + m * 512 + ncol) =
                    pack2h(__float2half(acc[mt][nt][h2 * 2]),
                           __float2half(acc[mt][nt][h2 * 2 + 1]));
            }
        }
}

// ---------------------------------------------------------------------------
// gemmo: out proj + residual -> f32 Y
// ---------------------------------------------------------------------------
__global__ __launch_bounds__(256)
void gemmo_k(const f16* __restrict__ A, const f16* __restrict__ Bw,
             const float* __restrict__ R, float* __restrict__ Yf)
{
    __shared__ __align__(16) char sm[SM_G];
    const int tid = threadIdx.x, lane = tid & 31, wi = tid >> 5;
    const int m0 = blockIdx.y * 128, n0 = blockIdx.x * 128;
    const int m0w = (wi >> 2) * 64, n0w = (wi & 3) * 32;
    const u32 sb = cvta_smem(sm);
    const int r = tid >> 1, hf = tid & 1;
    const u32 soff = (u32)(r * 80 + hf * 32);

    float acc[4][4][4];
#pragma unroll
    for (int i = 0; i < 4; i++)
#pragma unroll
        for (int j = 0; j < 4; j++)
#pragma unroll
            for (int q = 0; q < 4; q++) acc[i][j][q] = 0.f;

    auto load_stage = [&](int c, u32 sbuf) {
        const size_t ao = (size_t)(m0 + r) * 512 + c * 32 + hf * 16;
        const size_t bo = (size_t)(n0 + r) * 512 + c * 32 + hf * 16;
        cp16(sbuf + soff,             A + ao);
        cp16(sbuf + soff + 16,        A + ao + 8);
        cp16(sbuf + TILE + soff,      Bw + bo);
        cp16(sbuf + TILE + soff + 16, Bw + bo + 8);
    };

    load_stage(0, sb);
    cp_commit();
    for (int c = 0; c < 16; c++) {
        const u32 cur = sb + (u32)((c & 1) * G_BUF);
        if (c + 1 < 16) {
            load_stage(c + 1, sb + (u32)(((c + 1) & 1) * G_BUF));
            cp_commit();
            cp_wait1();
        } else {
            cp_wait0();
        }
        __syncthreads();
        compute_ff44(acc, cur, m0w, n0w, lane);
        __syncthreads();
    }

    const int g = lane >> 2, tg = lane & 3;
#pragma unroll
    for (int mt = 0; mt < 4; mt++)
#pragma unroll
        for (int h2 = 0; h2 < 2; h2++) {
            const size_t m = (size_t)(m0 + m0w + mt * 16 + h2 * 8 + g);
#pragma unroll
            for (int nt = 0; nt < 4; nt++) {
                const int ncol = n0 + n0w + nt * 8 + tg * 2;
                const float2 rv = *(const float2*)(R + m * 512 + ncol);
                *(float2*)(Yf + m * 512 + ncol) =
                    make_float2(acc[mt][nt][h2 * 2] + rv.x,
                                acc[mt][nt][h2 * 2 + 1] + rv.y);
            }
        }
}

// ---------------------------------------------------------------------------
// Scores: fp16 MMA -> exp -> unnormalized P fp16 + rowsums.
// R15: mask via smem (coalesced), P staged in smem (pitch 272, conflict-free
// fragment stores) then coalesced uint4 writes (16 lanes per 256B row).
// ---------------------------------------------------------------------------
__global__ __launch_bounds__(256)
void scores_k(const f16* __restrict__ Qh, const f16* __restrict__ Kh,
              const unsigned char* __restrict__ mask,
              f16* __restrict__ Ph, float* __restrict__ rowsum)
{
    __shared__ __align__(16) char sm[SM_SC];
    const int tid = threadIdx.x, lane = tid & 31, wi = tid >> 5;
    const int bh = blockIdx.z, b_ = bh >> 3, h_ = bh & 7;
    const int q0 = blockIdx.y * 128, kt0 = blockIdx.x * 128;
    const int m0w = (wi >> 2) * 64, n0w = (wi & 3) * 32;
    const u32 sb = cvta_smem(sm);
    const int r = tid >> 1, hf = tid & 1;
    const u32 soff = (u32)(r * 80 + hf * 32);
    const int la15 = lane & 15, lc = lane >> 4;
    const int l7 = lane & 7, lb = (lane >> 3) & 1;

    float acc[4][4][4];
#pragma unroll
    for (int i = 0; i < 4; i++)
#pragma unroll
        for (int j = 0; j < 4; j++)
#pragma unroll
            for (int q = 0; q < 4; q++) acc[i][j][q] = 0.f;

#pragma unroll
    for (int c = 0; c < 2; c++) {
        const int k0 = h_ * 64 + c * 32;
        {
            const uint4* qp = (const uint4*)(Qh + (size_t)(b_ * S + q0 + r) * 512 + k0 + hf * 16);
            *(uint4*)(sm + SC_Q + soff)      = qp[0];
            *(uint4*)(sm + SC_Q + soff + 16) = qp[1];
        }
        {
            const uint4* kp = (const uint4*)(Kh + (size_t)(b_ * S + kt0 + r) * 512 + k0 + hf * 16);
            *(uint4*)(sm + SC_K + soff)      = kp[0];
            *(uint4*)(sm + SC_K + soff + 16) = kp[1];
        }
        __syncthreads();
#pragma unroll
        for (int ks = 0; ks < 2; ks++) {
            const u32 ko = (u32)(ks * 32);
            u32 a4[4][4];
#pragma unroll
            for (int mt = 0; mt < 4; mt++) {
                u32 a = sb + SC_Q + (u32)((m0w + mt * 16 + la15) * 80) + ko + lc * 16;
                ldsm4(a4[mt][0], a4[mt][1], a4[mt][2], a4[mt][3], a);
            }
            u32 b2[4][2];
#pragma unroll
            for (int nt = 0; nt < 4; nt++) {
                u32 a = sb + SC_K + (u32)((n0w + nt * 8 + l7) * 80) + ko + lb * 16;
                ldsm2(b2[nt][0], b2[nt][1], a);
            }
#pragma unroll
            for (int mt = 0; mt < 4; mt++)
#pragma unroll
                for (int nt = 0; nt < 4; nt++)
                    mma_ff(acc[mt][nt], a4[mt], b2[nt]);
        }
        __syncthreads();
    }

    // mask tile -> smem (coalesced: 8 lanes x 16B per 128B row)
    {
        const int mr = tid >> 3, c8 = tid & 7;
#pragma unroll
        for (int p = 0; p < 4; p++) {
            const int row = mr + p * 32;
            *(uint4*)(sm + SC_MK + row * 128 + c8 * 16) =
                *(const uint4*)(mask + (size_t)(b_ * S + q0 + row) * S + kt0 + c8 * 16);
        }
    }
    __syncthreads();

    // exp + mask + rowsum; pack fragments
    const int g = lane >> 2, tg = lane & 3;
    u32 pk[4][2][4];
#pragma unroll
    for (int mt = 0; mt < 4; mt++)
#pragma unroll
        for (int h2 = 0; h2 < 2; h2++) {
            const int srow = m0w + mt * 16 + h2 * 8 + g;
            float rs = 0.f;
#pragma unroll
            for (int nt = 0; nt < 4; nt++) {
                const int col = n0w + nt * 8 + tg * 2;
                const unsigned short mv =
                    *(const unsigned short*)(sm + SC_MK + srow * 128 + col);
                const float e0 = (mv & 0xff) ? 0.f : __expf(acc[mt][nt][h2 * 2]     * 0.125f);
                const float e1 = (mv >> 8)   ? 0.f : __expf(acc[mt][nt][h2 * 2 + 1] * 0.125f);
                pk[mt][h2][nt] = pack2h(__float2half(e0), __float2half(e1));
                rs += e0 + e1;
            }
            rs += __shfl_xor_sync(0xffffffffu, rs, 1);
            rs += __shfl_xor_sync(0xffffffffu, rs, 2);
            if (tg == 0) atomicAdd(&rowsum[(size_t)bh * S + q0 + srow], rs);
        }
    __syncthreads();

    // stage P tile to smem, pitch 272 (bank-exact conflict-free: 4g+tg)
#pragma unroll
    for (int mt = 0; mt < 4; mt++)
#pragma unroll
        for (int h2 = 0; h2 < 2; h2++) {
            const int srow = m0w + mt * 16 + h2 * 8 + g;
#pragma unroll
            for (int nt = 0; nt < 4; nt++)
                *(u32*)(sm + SC_PST + srow * 272 + (n0w + nt * 8 + tg * 2) * 2) =
                    pk[mt][h2][nt];
        }
    __syncthreads();

    // coalesced write: 16 lanes cover one 256B row
    {
        const int orow = tid >> 4, l16 = tid & 15;
#pragma unroll
        for (int p = 0; p < 8; p++) {
            const int row = orow + p * 16;
            const uint4 v = *(const uint4*)(sm + SC_PST + row * 272 + l16 * 16);
            *(uint4*)(Ph + ((size_t)bh * S + q0 + row) * S + kt0 + l16 * 8) = v;
        }
    }
}

// ---------------------------------------------------------------------------
// PV: O = rinv * (P_unnorm @ V); normalized f32 attn written coalesced
// (8 lanes per 256B row) from the staged smem P chunk.
// ---------------------------------------------------------------------------
__global__ __launch_bounds__(256)
void pv_k(const f16* __restrict__ Ph, const f16* __restrict__ Vh,
          const float* __restrict__ rowsum, float* __restrict__ attn,
          f16* __restrict__ Oh)
{
    extern __shared__ __align__(16) char sm[];
    const int tid = threadIdx.x, lane = tid & 31, wi = tid >> 5;
    const int bh = blockIdx.y, b_ = bh >> 3, h_ = bh & 7;
    const int q0 = blockIdx.x * 128;
    const int m0w = (wi >> 1) * 32, n0w = (wi & 1) * 32;
    const u32 sb = cvta_smem(sm);
    float* rinv_s = (float*)(sm + PV_RI);
    if (tid < 128) rinv_s[tid] = 1.0f / rowsum[(size_t)bh * S + q0 + tid];
    __syncthreads();

    const int r = tid >> 1, hf = tid & 1;
    const int vr = tid >> 3, vs = tid & 7;
    const int la15 = lane & 15, lc = lane >> 4;
    const u32 pbu[2] = {sb + PV_P0, sb + PV_P1};
    const u32 vbu[2] = {sb + PV_V0, sb + PV_V1};
    char* const pbc[2] = {sm + PV_P0, sm + PV_P1};
    const f16* Prow = Ph + ((size_t)bh * S + q0 + r) * S;

    float acc[2][4][4];
#pragma unroll
    for (int i = 0; i < 2; i++)
#pragma unroll
        for (int j = 0; j < 4; j++)
#pragma unroll
            for (int q = 0; q < 4; q++) acc[i][j][q] = 0.f;

    auto load_stage = [&](int c, int buf) {
        const int kt = c * 64;
#pragma unroll
        for (int j = 0; j < 4; j++)
            cp16(pbu[buf] + (u32)(r * 144 + hf * 64 + j * 16),
                 Prow + kt + hf * 32 + j * 8);
#pragma unroll
        for (int j = 0; j < 2; j++) {
            const int row = vr + j * 32;
            cp16(vbu[buf] + (u32)(row * 144 + vs * 16),
                 Vh + (size_t)(b_ * S + kt + row) * 512 + h_ * 64 + vs * 8);
        }
    };

    load_stage(0, 0);
    cp_commit();
    for (int c = 0; c < 32; c++) {
        const int cur = c & 1;
        if (c + 1 < 32) {
            load_stage(c + 1, cur ^ 1);
            cp_commit();
            cp_wait1();
        } else {
            cp_wait0();
        }
        __syncthreads();
#pragma unroll
        for (int ks = 0; ks < 4; ks++) {
            u32 a4[2][4];
#pragma unroll
            for (int mt = 0; mt < 2; mt++) {
                u32 a = pbu[cur] + (u32)((m0w + mt * 16 + la15) * 144 + ks * 32 + lc * 16);
                ldsm4(a4[mt][0], a4[mt][1], a4[mt][2], a4[mt][3], a);
            }
            u32 b2[4][2];
#pragma unroll
            for (int nt = 0; nt < 4; nt++) {
                u32 a = vbu[cur] + (u32)((ks * 16 + la15) * 144 + (n0w + nt * 8) * 2);
                ldsm2t(b2[nt][0], b2[nt][1], a);
            }
#pragma unroll
            for (int mt = 0; mt < 2; mt++)
#pragma unroll
                for (int nt = 0; nt < 4; nt++)
                    mma_ff(acc[mt][nt], a4[mt], b2[nt]);
        }
        // normalized attn write, coalesced: 8 lanes x 32B cover one 256B row
        {
            const int kt = c * 64;
            const int r32 = tid >> 3, c8 = tid & 7;
#pragma unroll
            for (int p = 0; p < 4; p++) {
                const int row = r32 + p * 32;
                const float rr = rinv_s[row];
                const uint4 w4 = *(const uint4*)(pbc[cur] + row * 144 + c8 * 16);
                const u32 w[4] = {w4.x, w4.y, w4.z, w4.w};
                float o[8];
#pragma unroll
                for (int e = 0; e < 4; e++) {
                    o[2 * e]     = __half2float(__ushort_as_half((unsigned short)(w[e] & 0xffff))) * rr;
                    o[2 * e + 1] = __half2float(__ushort_as_half((unsigned short)(w[e] >> 16))) * rr;
                }
                float* dst = attn + ((size_t)bh * S + q0 + row) * S + kt + c8 * 8;
                *(float4*)dst       = make_float4(o[0], o[1], o[2], o[3]);
                *(float4*)(dst + 4) = make_float4(o[4], o[5], o[6], o[7]);
            }
        }
        __syncthreads();
    }

    const int g = lane >> 2, tg = lane & 3;
#pragma unroll
    for (int mt = 0; mt < 2; mt++)
#pragma unroll
        for (int h2 = 0; h2 < 2; h2++) {
            const int row = m0w + mt * 16 + h2 * 8 + g;
            const float rr = rinv_s[row];
            const size_t m = (size_t)(b_ * S + q0 + row);
#pragma unroll
            for (int nt = 0; nt < 4; nt++) {
                const int ncol = h_ * 64 + n0w + nt * 8 + tg * 2;
                *(u32*)(Oh + m * 512 + ncol) =
                    pack2h(__float2half(acc[mt][nt][h2 * 2] * rr),
                           __float2half(acc[mt][nt][h2 * 2 + 1] * rr));
            }
        }
}

// ---------------------------------------------------------------------------
// Row LayerNorm
// ---------------------------------------------------------------------------
__global__ __launch_bounds__(128)
void ln_k(const float* __restrict__ X, const float* __restrict__ gam,
          const float* __restrict__ bet, float* __restrict__ out)
{
    __shared__ float red[4];
    const int row = blockIdx.x, tid = threadIdx.x;
    const int lane = tid & 31, wid = tid >> 5;
    const float4 x = *(const float4*)(X + (size_t)row * D + tid * 4);

    float s = x.x + x.y + x.z + x.w;
#pragma unroll
    for (int off = 16; off > 0; off >>= 1) s += __shfl_xor_sync(~0u, s, off);
    if (lane == 0) red[wid] = s;
    __syncthreads();
    const float mu = (red[0] + red[1] + red[2] + red[3]) * (1.0f / D);
    __syncthreads();

    const float4 dx = make_float4(x.x - mu, x.y - mu, x.z - mu, x.w - mu);
    float q = dx.x * dx.x + dx.y * dx.y + dx.z * dx.z + dx.w * dx.w;
#pragma unroll
    for (int off = 16; off > 0; off >>= 1) q += __shfl_xor_sync(~0u, q, off);
    if (lane == 0) red[wid] = q;
    __syncthreads();
    const float var = (red[0] + red[1] + red[2] + red[3]) * (1.0f / D);
    const float inv = rsqrtf(var + 1e-5f);

    const float4 g  = *(const float4*)(gam + tid * 4);
    const float4 bb = *(const float4*)(bet + tid * 4);
    float4 y;
    y.x = dx.x * inv * g.x + bb.x;
    y.y = dx.y * inv * g.y + bb.y;
    y.z = dx.z * inv * g.z + bb.z;
    y.w = dx.w * inv * g.w + bb.w;
    *(float4*)(out + (size_t)row * D + tid * 4) = y;
}

// ---------------------------------------------------------------------------
extern "C" void kernel_launch(void* const* d_in, const int* in_sizes, int n_in,
                              void* d_out, int out_size)
{
    (void)in_sizes; (void)n_in;
    const float* Xq = (const float*)d_in[0];
    const float* Xk = (const float*)d_in[1];
    const float* Xv = (const float*)d_in[2];
    const unsigned char* mask = (const unsigned char*)d_in[3];
    const float* Wq = (const float*)d_in[4];
    const float* Wk = (const float*)d_in[5];
    const float* Wv = (const float*)d_in[6];
    const float* Wo = (const float*)d_in[7];
    const float* gam = (const float*)d_in[8];
    const float* bet = (const float*)d_in[9];
    float* out = (float*)d_out;

    f16 *gWt, *gXh, *gQh, *gKh, *gVh, *gOh, *gPh;
    float *gY, *grs, *gfb;
    cudaGetSymbolAddress((void**)&gWt, g_Wt);
    cudaGetSymbolAddress((void**)&gXh, g_Xh);
    cudaGetSymbolAddress((void**)&gQh, g_Qh);
    cudaGetSymbolAddress((void**)&gKh, g_Kh);
    cudaGetSymbolAddress((void**)&gVh, g_Vh);
    cudaGetSymbolAddress((void**)&gOh, g_Oh);
    cudaGetSymbolAddress((void**)&gPh, g_Ph);
    cudaGetSymbolAddress((void**)&gY, g_Y);
    cudaGetSymbolAddress((void**)&grs, g_rowsum);
    cudaGetSymbolAddress((void**)&gfb, g_attn_fb);
    const size_t DD = (size_t)D * D;

    cudaFuncSetAttribute(pv_k, cudaFuncAttributeMaxDynamicSharedMemorySize, SM_PV);

    float* attnp = ((long long)out_size >= OUT_ELEMS + ATTN_ELEMS)
                       ? (out + OUT_ELEMS) : gfb;

    // 1) prep
    whalf_k<<<dim3(1024, 1, 4), 256>>>(Wq, Wk, Wv, Wo, gWt);
    xhalf_k<<<dim3(4096, 1, 3), 256>>>(Xq, Xk, Xv, gXh);
    cudaMemsetAsync(grs, 0, sizeof(float) * BH * S);

    // 2) projections (Q,K,V batched)
    gemmf3_k<<<dim3(4, 64, 3), 256>>>(gXh, gWt, gQh, gKh, gVh);

    // 3) scores -> unnormalized fp16 P + rowsums
    scores_k<<<dim3(16, 16, 32), 256>>>(gQh, gKh, mask, gPh, grs);

    // 4) PV + normalized attn write
    pv_k<<<dim3(16, 32), 256, SM_PV>>>(gPh, gVh, grs, attnp, gOh);

    // 5) out proj + residual, then LayerNorm
    gemmo_k<<<dim3(4, 64), 256>>>(gOh, gWt + 3 * DD, Xq, gY);
    ln_k<<<MTOK, 128>>>(gY, gam, bet, out);
}

// round 16
// speedup vs baseline: 3.2760x; 1.1196x over previous
#include <cuda_runtime.h>
#include <cuda_fp16.h>
#include <cstdint>

// ---------------------------------------------------------------------------
// MHA block, all fp16 mma.sync (error-budgeted) + R16: scores epilogue
// restructured (exp-then-mask, coalesced mask/rowsum/store; cp.async chunks).
// ---------------------------------------------------------------------------

using f16 = __half;
typedef unsigned int u32;
typedef unsigned long long u64;

namespace {
constexpr int B = 4, S = 2048, D = 512, H = 8, BH = 32, MTOK = 8192;
constexpr long long OUT_ELEMS  = (long long)MTOK * D;
constexpr long long ATTN_ELEMS = (long long)BH * S * (long long)S;

constexpr int TILE = 10240;                       // 128 x 80B
constexpr int G_BUF = 2 * TILE, SM_G = 2 * G_BUF;
// scores smem: 2 double-buffered QK chunk pairs; P stage (128x272) overlays
constexpr int SM_SC = 4 * TILE;                   // 40960 (P stage 34816 fits)
// pv smem: P 128x144B x2, V 64x144B x2, rinv
constexpr int PV_P0 = 0, PV_P1 = 18432, PV_V0 = 36864, PV_V1 = 46080,
              PV_RI = 55296, SM_PV = 55808;
}

// ---- device scratch ----------------------------------------------------------
__device__ f16   g_Wt[4][(size_t)D * D];
__device__ f16   g_Xh[3][(size_t)MTOK * D];
__device__ f16   g_Qh[(size_t)MTOK * D];
__device__ f16   g_Kh[(size_t)MTOK * D];
__device__ f16   g_Vh[(size_t)MTOK * D];
__device__ f16   g_Oh[(size_t)MTOK * D];
__device__ f16   g_Ph[(size_t)BH * S * (size_t)S];
__device__ float g_Y[(size_t)MTOK * D];
__device__ float g_rowsum[BH * S];
__device__ float g_attn_fb[(size_t)BH * S * (size_t)S];

// ---- PTX helpers ---------------------------------------------------------------
__device__ __forceinline__ u32 cvta_smem(const void* p) {
    u32 a;
    asm("{ .reg .u64 t; cvta.to.shared.u64 t, %1; cvt.u32.u64 %0, t; }"
        : "=r"(a) : "l"(p));
    return a;
}
__device__ __forceinline__ void ldsm4(u32& r0, u32& r1, u32& r2, u32& r3, u32 a) {
    asm volatile("ldmatrix.sync.aligned.m8n8.x4.shared.b16 {%0,%1,%2,%3}, [%4];"
                 : "=r"(r0), "=r"(r1), "=r"(r2), "=r"(r3) : "r"(a));
}
__device__ __forceinline__ void ldsm2(u32& r0, u32& r1, u32 a) {
    asm volatile("ldmatrix.sync.aligned.m8n8.x2.shared.b16 {%0,%1}, [%2];"
                 : "=r"(r0), "=r"(r1) : "r"(a));
}
__device__ __forceinline__ void ldsm2t(u32& r0, u32& r1, u32 a) {
    asm volatile("ldmatrix.sync.aligned.m8n8.x2.trans.shared.b16 {%0,%1}, [%2];"
                 : "=r"(r0), "=r"(r1) : "r"(a));
}
__device__ __forceinline__ void mma_ff(float* c, const u32* a, const u32* b) {
    asm volatile(
        "mma.sync.aligned.m16n8k16.row.col.f32.f16.f16.f32 "
        "{%0,%1,%2,%3}, {%4,%5,%6,%7}, {%8,%9}, {%0,%1,%2,%3};"
        : "+f"(c[0]), "+f"(c[1]), "+f"(c[2]), "+f"(c[3])
        : "r"(a[0]), "r"(a[1]), "r"(a[2]), "r"(a[3]), "r"(b[0]), "r"(b[1]));
}
__device__ __forceinline__ void cp16(u32 dst, const void* src) {
    asm volatile("cp.async.cg.shared.global [%0], [%1], 16;" :: "r"(dst), "l"(src));
}
__device__ __forceinline__ void cp_commit() {
    asm volatile("cp.async.commit_group;" ::: "memory");
}
__device__ __forceinline__ void cp_wait0() {
    asm volatile("cp.async.wait_group 0;" ::: "memory");
}
__device__ __forceinline__ void cp_wait1() {
    asm volatile("cp.async.wait_group 1;" ::: "memory");
}
__device__ __forceinline__ u32 pack2h(f16 a, f16 b) {
    return (u32)__half_as_ushort(a) | ((u32)__half_as_ushort(b) << 16);
}

// ---------------------------------------------------------------------------
// Prep
// ---------------------------------------------------------------------------
__global__ void whalf_k(const float* __restrict__ w0, const float* __restrict__ w1,
                        const float* __restrict__ w2, const float* __restrict__ w3,
                        f16* __restrict__ o) {
    const float* w = (blockIdx.z == 0) ? w0 : (blockIdx.z == 1) ? w1
                   : (blockIdx.z == 2) ? w2 : w3;
    f16* t = o + (size_t)blockIdx.z * D * D;
    int i = blockIdx.x * 256 + threadIdx.x;
    int k = i >> 9, n = i & 511;
    t[(size_t)n * 512 + k] = __float2half(w[i]);
}
__global__ void xhalf_k(const float* __restrict__ x0, const float* __restrict__ x1,
                        const float* __restrict__ x2, f16* __restrict__ o) {
    const float* x = (blockIdx.z == 0) ? x0 : (blockIdx.z == 1) ? x1 : x2;
    f16* t = o + (size_t)blockIdx.z * MTOK * D;
    const size_t i = ((size_t)blockIdx.x * 256 + threadIdx.x) * 4;
    float4 v = *(const float4*)(x + i);
    *(uint2*)(t + i) = make_uint2(pack2h(__float2half(v.x), __float2half(v.y)),
                                  pack2h(__float2half(v.z), __float2half(v.w)));
}

// ---------------------------------------------------------------------------
// One BK=32 fp16 stage, warp tile 64x32  (A at sbuf, B at sbuf+TILE)
// ---------------------------------------------------------------------------
__device__ __forceinline__ void compute_ff44(float acc[4][4][4], u32 sbuf,
                                             int m0w, int n0w, int lane)
{
    const int la15 = lane & 15, lc = lane >> 4;
    const int l7 = lane & 7, lb = (lane >> 3) & 1;
#pragma unroll
    for (int ks = 0; ks < 2; ks++) {
        const u32 ko = (u32)(ks * 32);
        u32 a4[4][4];
#pragma unroll
        for (int mt = 0; mt < 4; mt++) {
            u32 a = sbuf + (u32)((m0w + mt * 16 + la15) * 80) + ko + lc * 16;
            ldsm4(a4[mt][0], a4[mt][1], a4[mt][2], a4[mt][3], a);
        }
        u32 b2[4][2];
#pragma unroll
        for (int nt = 0; nt < 4; nt++) {
            u32 a = sbuf + TILE + (u32)((n0w + nt * 8 + l7) * 80) + ko + lb * 16;
            ldsm2(b2[nt][0], b2[nt][1], a);
        }
#pragma unroll
        for (int mt = 0; mt < 4; mt++)
#pragma unroll
            for (int nt = 0; nt < 4; nt++)
                mma_ff(acc[mt][nt], a4[mt], b2[nt]);
    }
}

// ---------------------------------------------------------------------------
// gemmf3: batched Q/K/V projections
// ---------------------------------------------------------------------------
__global__ __launch_bounds__(256)
void gemmf3_k(const f16* __restrict__ Xh, const f16* __restrict__ Wt,
              f16* __restrict__ C0, f16* __restrict__ C1, f16* __restrict__ C2)
{
    __shared__ __align__(16) char sm[SM_G];
    const f16* A = Xh + (size_t)blockIdx.z * MTOK * D;
    const f16* Bw = Wt + (size_t)blockIdx.z * D * D;
    f16* C = (blockIdx.z == 0) ? C0 : (blockIdx.z == 1) ? C1 : C2;

    const int tid = threadIdx.x, lane = tid & 31, wi = tid >> 5;
    const int m0 = blockIdx.y * 128, n0 = blockIdx.x * 128;
    const int m0w = (wi >> 2) * 64, n0w = (wi & 3) * 32;
    const u32 sb = cvta_smem(sm);
    const int r = tid >> 1, hf = tid & 1;
    const u32 soff = (u32)(r * 80 + hf * 32);

    float acc[4][4][4];
#pragma unroll
    for (int i = 0; i < 4; i++)
#pragma unroll
        for (int j = 0; j < 4; j++)
#pragma unroll
            for (int q = 0; q < 4; q++) acc[i][j][q] = 0.f;

    auto load_stage = [&](int c, u32 sbuf) {
        const size_t ao = (size_t)(m0 + r) * 512 + c * 32 + hf * 16;
        const size_t bo = (size_t)(n0 + r) * 512 + c * 32 + hf * 16;
        cp16(sbuf + soff,             A + ao);
        cp16(sbuf + soff + 16,        A + ao + 8);
        cp16(sbuf + TILE + soff,      Bw + bo);
        cp16(sbuf + TILE + soff + 16, Bw + bo + 8);
    };

    load_stage(0, sb);
    cp_commit();
    for (int c = 0; c < 16; c++) {
        const u32 cur = sb + (u32)((c & 1) * G_BUF);
        if (c + 1 < 16) {
            load_stage(c + 1, sb + (u32)(((c + 1) & 1) * G_BUF));
            cp_commit();
            cp_wait1();
        } else {
            cp_wait0();
        }
        __syncthreads();
        compute_ff44(acc, cur, m0w, n0w, lane);
        __syncthreads();
    }

    const int g = lane >> 2, tg = lane & 3;
#pragma unroll
    for (int mt = 0; mt < 4; mt++)
#pragma unroll
        for (int h2 = 0; h2 < 2; h2++) {
            const size_t m = (size_t)(m0 + m0w + mt * 16 + h2 * 8 + g);
#pragma unroll
            for (int nt = 0; nt < 4; nt++) {
                const int ncol = n0 + n0w + nt * 8 + tg * 2;
                *(u32*)(C + m * 512 + ncol) =
                    pack2h(__float2half(acc[mt][nt][h2 * 2]),
                           __float2half(acc[mt][nt][h2 * 2 + 1]));
            }
        }
}

// ---------------------------------------------------------------------------
// gemmo: out proj + residual -> f32 Y
// ---------------------------------------------------------------------------
__global__ __launch_bounds__(256)
void gemmo_k(const f16* __restrict__ A, const f16* __restrict__ Bw,
             const float* __restrict__ R, float* __restrict__ Yf)
{
    __shared__ __align__(16) char sm[SM_G];
    const int tid = threadIdx.x, lane = tid & 31, wi = tid >> 5;
    const int m0 = blockIdx.y * 128, n0 = blockIdx.x * 128;
    const int m0w = (wi >> 2) * 64, n0w = (wi & 3) * 32;
    const u32 sb = cvta_smem(sm);
    const int r = tid >> 1, hf = tid & 1;
    const u32 soff = (u32)(r * 80 + hf * 32);

    float acc[4][4][4];
#pragma unroll
    for (int i = 0; i < 4; i++)
#pragma unroll
        for (int j = 0; j < 4; j++)
#pragma unroll
            for (int q = 0; q < 4; q++) acc[i][j][q] = 0.f;

    auto load_stage = [&](int c, u32 sbuf) {
        const size_t ao = (size_t)(m0 + r) * 512 + c * 32 + hf * 16;
        const size_t bo = (size_t)(n0 + r) * 512 + c * 32 + hf * 16;
        cp16(sbuf + soff,             A + ao);
        cp16(sbuf + soff + 16,        A + ao + 8);
        cp16(sbuf + TILE + soff,      Bw + bo);
        cp16(sbuf + TILE + soff + 16, Bw + bo + 8);
    };

    load_stage(0, sb);
    cp_commit();
    for (int c = 0; c < 16; c++) {
        const u32 cur = sb + (u32)((c & 1) * G_BUF);
        if (c + 1 < 16) {
            load_stage(c + 1, sb + (u32)(((c + 1) & 1) * G_BUF));
            cp_commit();
            cp_wait1();
        } else {
            cp_wait0();
        }
        __syncthreads();
        compute_ff44(acc, cur, m0w, n0w, lane);
        __syncthreads();
    }

    const int g = lane >> 2, tg = lane & 3;
#pragma unroll
    for (int mt = 0; mt < 4; mt++)
#pragma unroll
        for (int h2 = 0; h2 < 2; h2++) {
            const size_t m = (size_t)(m0 + m0w + mt * 16 + h2 * 8 + g);
#pragma unroll
            for (int nt = 0; nt < 4; nt++) {
                const int ncol = n0 + n0w + nt * 8 + tg * 2;
                const float2 rv = *(const float2*)(R + m * 512 + ncol);
                *(float2*)(Yf + m * 512 + ncol) =
                    make_float2(acc[mt][nt][h2 * 2] + rv.x,
                                acc[mt][nt][h2 * 2 + 1] + rv.y);
            }
        }
}

// ---------------------------------------------------------------------------
// Scores (R16): cp.async both DK chunks; exp-only fragments staged to smem;
// mask + rowsum + P store all in the coalesced write phase.
// ---------------------------------------------------------------------------
__global__ __launch_bounds__(256)
void scores_k(const f16* __restrict__ Qh, const f16* __restrict__ Kh,
              const unsigned char* __restrict__ mask,
              f16* __restrict__ Ph, float* __restrict__ rowsum)
{
    __shared__ __align__(16) char sm[SM_SC];
    const int tid = threadIdx.x, lane = tid & 31, wi = tid >> 5;
    const int bh = blockIdx.z, b_ = bh >> 3, h_ = bh & 7;
    const int q0 = blockIdx.y * 128, kt0 = blockIdx.x * 128;
    const int m0w = (wi >> 2) * 64, n0w = (wi & 3) * 32;
    const u32 sb = cvta_smem(sm);
    const int r = tid >> 1, hf = tid & 1;
    const u32 soff = (u32)(r * 80 + hf * 32);

    // issue both DK chunks (double-buffered)
#pragma unroll
    for (int c = 0; c < 2; c++) {
        const int k0 = h_ * 64 + c * 32;
        const f16* qa = Qh + (size_t)(b_ * S + q0 + r) * 512 + k0 + hf * 16;
        const f16* ka = Kh + (size_t)(b_ * S + kt0 + r) * 512 + k0 + hf * 16;
        const u32 base = sb + (u32)(c * 2 * TILE);
        cp16(base + soff,             qa);
        cp16(base + soff + 16,        qa + 8);
        cp16(base + TILE + soff,      ka);
        cp16(base + TILE + soff + 16, ka + 8);
        cp_commit();
    }

    float acc[4][4][4];
#pragma unroll
    for (int i = 0; i < 4; i++)
#pragma unroll
        for (int j = 0; j < 4; j++)
#pragma unroll
            for (int q = 0; q < 4; q++) acc[i][j][q] = 0.f;

    cp_wait1();
    __syncthreads();
    compute_ff44(acc, sb, m0w, n0w, lane);
    cp_wait0();
    __syncthreads();
    compute_ff44(acc, sb + 2 * TILE, m0w, n0w, lane);
    __syncthreads();          // chunk smem dead; safe to overlay P stage

    // stage exp fragments (pitch 272; 4g+tg -> conflict-free)
    const int g = lane >> 2, tg = lane & 3;
#pragma unroll
    for (int mt = 0; mt < 4; mt++)
#pragma unroll
        for (int h2 = 0; h2 < 2; h2++) {
            const int srow = m0w + mt * 16 + h2 * 8 + g;
#pragma unroll
            for (int nt = 0; nt < 4; nt++) {
                const int col = n0w + nt * 8 + tg * 2;
                const float e0 = __expf(acc[mt][nt][h2 * 2]     * 0.125f);
                const float e1 = __expf(acc[mt][nt][h2 * 2 + 1] * 0.125f);
                *(u32*)(sm + srow * 272 + col * 2) =
                    pack2h(__float2half(e0), __float2half(e1));
            }
        }
    __syncthreads();

    // coalesced write phase: mask (u64 gmem) + rowsum + P store, 16 lanes/row
    const int orow = tid >> 4, l16 = tid & 15;
#pragma unroll
    for (int p = 0; p < 8; p++) {
        const int row = orow + p * 16;
        uint4 v = *(const uint4*)(sm + row * 272 + l16 * 16);
        const u64 mv = *(const u64*)(mask + (size_t)(b_ * S + q0 + row) * S
                                          + kt0 + l16 * 8);
        u32 w[4] = {v.x, v.y, v.z, v.w};
        float rs = 0.f;
#pragma unroll
        for (int e = 0; e < 4; e++) {
            if ((mv >> (16 * e)) & 0xffULL) w[e] &= 0xffff0000u;
            else rs += __half2float(__ushort_as_half((unsigned short)(w[e] & 0xffff)));
            if ((mv >> (16 * e + 8)) & 0xffULL) w[e] &= 0x0000ffffu;
            else rs += __half2float(__ushort_as_half((unsigned short)(w[e] >> 16)));
        }
        *(uint4*)(Ph + ((size_t)bh * S + q0 + row) * S + kt0 + l16 * 8) =
            make_uint4(w[0], w[1], w[2], w[3]);
#pragma unroll
        for (int off = 8; off > 0; off >>= 1)
            rs += __shfl_xor_sync(0xffffffffu, rs, off);
        if (l16 == 0) atomicAdd(&rowsum[(size_t)bh * S + q0 + row], rs);
    }
}

// ---------------------------------------------------------------------------
// PV: O = rinv * (P_unnorm @ V); normalized f32 attn written coalesced.
// ---------------------------------------------------------------------------
__global__ __launch_bounds__(256)
void pv_k(const f16* __restrict__ Ph, const f16* __restrict__ Vh,
          const float* __restrict__ rowsum, float* __restrict__ attn,
          f16* __restrict__ Oh)
{
    extern __shared__ __align__(16) char sm[];
    const int tid = threadIdx.x, lane = tid & 31, wi = tid >> 5;
    const int bh = blockIdx.y, b_ = bh >> 3, h_ = bh & 7;
    const int q0 = blockIdx.x * 128;
    const int m0w = (wi >> 1) * 32, n0w = (wi & 1) * 32;
    const u32 sb = cvta_smem(sm);
    float* rinv_s = (float*)(sm + PV_RI);
    if (tid < 128) rinv_s[tid] = 1.0f / rowsum[(size_t)bh * S + q0 + tid];
    __syncthreads();

    const int r = tid >> 1, hf = tid & 1;
    const int vr = tid >> 3, vs = tid & 7;
    const int la15 = lane & 15, lc = lane >> 4;
    const u32 pbu[2] = {sb + PV_P0, sb + PV_P1};
    const u32 vbu[2] = {sb + PV_V0, sb + PV_V1};
    char* const pbc[2] = {sm + PV_P0, sm + PV_P1};
    const f16* Prow = Ph + ((size_t)bh * S + q0 + r) * S;

    float acc[2][4][4];
#pragma unroll
    for (int i = 0; i < 2; i++)
#pragma unroll
        for (int j = 0; j < 4; j++)
#pragma unroll
            for (int q = 0; q < 4; q++) acc[i][j][q] = 0.f;

    auto load_stage = [&](int c, int buf) {
        const int kt = c * 64;
#pragma unroll
        for (int j = 0; j < 4; j++)
            cp16(pbu[buf] + (u32)(r * 144 + hf * 64 + j * 16),
                 Prow + kt + hf * 32 + j * 8);
#pragma unroll
        for (int j = 0; j < 2; j++) {
            const int row = vr + j * 32;
            cp16(vbu[buf] + (u32)(row * 144 + vs * 16),
                 Vh + (size_t)(b_ * S + kt + row) * 512 + h_ * 64 + vs * 8);
        }
    };

    load_stage(0, 0);
    cp_commit();
    for (int c = 0; c < 32; c++) {
        const int cur = c & 1;
        if (c + 1 < 32) {
            load_stage(c + 1, cur ^ 1);
            cp_commit();
            cp_wait1();
        } else {
            cp_wait0();
        }
        __syncthreads();
#pragma unroll
        for (int ks = 0; ks < 4; ks++) {
            u32 a4[2][4];
#pragma unroll
            for (int mt = 0; mt < 2; mt++) {
                u32 a = pbu[cur] + (u32)((m0w + mt * 16 + la15) * 144 + ks * 32 + lc * 16);
                ldsm4(a4[mt][0], a4[mt][1], a4[mt][2], a4[mt][3], a);
            }
            u32 b2[4][2];
#pragma unroll
            for (int nt = 0; nt < 4; nt++) {
                u32 a = vbu[cur] + (u32)((ks * 16 + la15) * 144 + (n0w + nt * 8) * 2);
                ldsm2t(b2[nt][0], b2[nt][1], a);
            }
#pragma unroll
            for (int mt = 0; mt < 2; mt++)
#pragma unroll
                for (int nt = 0; nt < 4; nt++)
                    mma_ff(acc[mt][nt], a4[mt], b2[nt]);
        }
        // normalized attn write, coalesced: 8 lanes x 32B per 256B row
        {
            const int kt = c * 64;
            const int r32 = tid >> 3, c8 = tid & 7;
#pragma unroll
            for (int p = 0; p < 4; p++) {
                const int row = r32 + p * 32;
                const float rr = rinv_s[row];
                const uint4 w4 = *(const uint4*)(pbc[cur] + row * 144 + c8 * 16);
                const u32 w[4] = {w4.x, w4.y, w4.z, w4.w};
                float o[8];
#pragma unroll
                for (int e = 0; e < 4; e++) {
                    o[2 * e]     = __half2float(__ushort_as_half((unsigned short)(w[e] & 0xffff))) * rr;
                    o[2 * e + 1] = __half2float(__ushort_as_half((unsigned short)(w[e] >> 16))) * rr;
                }
                float* dst = attn + ((size_t)bh * S + q0 + row) * S + kt + c8 * 8;
                *(float4*)dst       = make_float4(o[0], o[1], o[2], o[3]);
                *(float4*)(dst + 4) = make_float4(o[4], o[5], o[6], o[7]);
            }
        }
        __syncthreads();
    }

    const int g = lane >> 2, tg = lane & 3;
#pragma unroll
    for (int mt = 0; mt < 2; mt++)
#pragma unroll
        for (int h2 = 0; h2 < 2; h2++) {
            const int row = m0w + mt * 16 + h2 * 8 + g;
            const float rr = rinv_s[row];
            const size_t m = (size_t)(b_ * S + q0 + row);
#pragma unroll
            for (int nt = 0; nt < 4; nt++) {
                const int ncol = h_ * 64 + n0w + nt * 8 + tg * 2;
                *(u32*)(Oh + m * 512 + ncol) =
                    pack2h(__float2half(acc[mt][nt][h2 * 2] * rr),
                           __float2half(acc[mt][nt][h2 * 2 + 1] * rr));
            }
        }
}

// ---------------------------------------------------------------------------
// Row LayerNorm
// ---------------------------------------------------------------------------
__global__ __launch_bounds__(128)
void ln_k(const float* __restrict__ X, const float* __restrict__ gam,
          const float* __restrict__ bet, float* __restrict__ out)
{
    __shared__ float red[4];
    const int row = blockIdx.x, tid = threadIdx.x;
    const int lane = tid & 31, wid = tid >> 5;
    const float4 x = *(const float4*)(X + (size_t)row * D + tid * 4);

    float s = x.x + x.y + x.z + x.w;
#pragma unroll
    for (int off = 16; off > 0; off >>= 1) s += __shfl_xor_sync(~0u, s, off);
    if (lane == 0) red[wid] = s;
    __syncthreads();
    const float mu = (red[0] + red[1] + red[2] + red[3]) * (1.0f / D);
    __syncthreads();

    const float4 dx = make_float4(x.x - mu, x.y - mu, x.z - mu, x.w - mu);
    float q = dx.x * dx.x + dx.y * dx.y + dx.z * dx.z + dx.w * dx.w;
#pragma unroll
    for (int off = 16; off > 0; off >>= 1) q += __shfl_xor_sync(~0u, q, off);
    if (lane == 0) red[wid] = q;
    __syncthreads();
    const float var = (red[0] + red[1] + red[2] + red[3]) * (1.0f / D);
    const float inv = rsqrtf(var + 1e-5f);

    const float4 g  = *(const float4*)(gam + tid * 4);
    const float4 bb = *(const float4*)(bet + tid * 4);
    float4 y;
    y.x = dx.x * inv * g.x + bb.x;
    y.y = dx.y * inv * g.y + bb.y;
    y.z = dx.z * inv * g.z + bb.z;
    y.w = dx.w * inv * g.w + bb.w;
    *(float4*)(out + (size_t)row * D + tid * 4) = y;
}

// ---------------------------------------------------------------------------
extern "C" void kernel_launch(void* const* d_in, const int* in_sizes, int n_in,
                              void* d_out, int out_size)
{
    (void)in_sizes; (void)n_in;
    const float* Xq = (const float*)d_in[0];
    const float* Xk = (const float*)d_in[1];
    const float* Xv = (const float*)d_in[2];
    const unsigned char* mask = (const unsigned char*)d_in[3];
    const float* Wq = (const float*)d_in[4];
    const float* Wk = (const float*)d_in[5];
    const float* Wv = (const float*)d_in[6];
    const float* Wo = (const float*)d_in[7];
    const float* gam = (const float*)d_in[8];
    const float* bet = (const float*)d_in[9];
    float* out = (float*)d_out;

    f16 *gWt, *gXh, *gQh, *gKh, *gVh, *gOh, *gPh;
    float *gY, *grs, *gfb;
    cudaGetSymbolAddress((void**)&gWt, g_Wt);
    cudaGetSymbolAddress((void**)&gXh, g_Xh);
    cudaGetSymbolAddress((void**)&gQh, g_Qh);
    cudaGetSymbolAddress((void**)&gKh, g_Kh);
    cudaGetSymbolAddress((void**)&gVh, g_Vh);
    cudaGetSymbolAddress((void**)&gOh, g_Oh);
    cudaGetSymbolAddress((void**)&gPh, g_Ph);
    cudaGetSymbolAddress((void**)&gY, g_Y);
    cudaGetSymbolAddress((void**)&grs, g_rowsum);
    cudaGetSymbolAddress((void**)&gfb, g_attn_fb);
    const size_t DD = (size_t)D * D;

    cudaFuncSetAttribute(pv_k, cudaFuncAttributeMaxDynamicSharedMemorySize, SM_PV);

    float* attnp = ((long long)out_size >= OUT_ELEMS + ATTN_ELEMS)
                       ? (out + OUT_ELEMS) : gfb;

    // 1) prep
    whalf_k<<<dim3(1024, 1, 4), 256>>>(Wq, Wk, Wv, Wo, gWt);
    xhalf_k<<<dim3(4096, 1, 3), 256>>>(Xq, Xk, Xv, gXh);
    cudaMemsetAsync(grs, 0, sizeof(float) * BH * S);

    // 2) projections (Q,K,V batched)
    gemmf3_k<<<dim3(4, 64, 3), 256>>>(gXh, gWt, gQh, gKh, gVh);

    // 3) scores -> unnormalized fp16 P + rowsums
    scores_k<<<dim3(16, 16, 32), 256>>>(gQh, gKh, mask, gPh, grs);

    // 4) PV + normalized attn write
    pv_k<<<dim3(16, 32), 256, SM_PV>>>(gPh, gVh, grs, attnp, gOh);

    // 5) out proj + residual, then LayerNorm
    gemmo_k<<<dim3(4, 64), 256>>>(gOh, gWt + 3 * DD, Xq, gY);
    ln_k<<<MTOK, 128>>>(gY, gam, bet, out);
}